// round 1
// baseline (speedup 1.0000x reference)
#include <cuda_runtime.h>
#include <cuda_bf16.h>

// ---------------------------------------------------------------------------
// LinearAttention: qkv = Wqkv@x ; q=softmax_d(q)*scale ; k=softmax_t(k)
// ctx = k@v^T (64x64 per b,h) ; Weff = Wout*ctx fold ; y = Weff@q + b_out
// GroupNorm(1) over (c,t) per batch.
// b=16, c=512, t=4096, heads=8, dh=64, hidden=512
// ---------------------------------------------------------------------------

#define B   16
#define C   512
#define T   4096
#define H   8
#define DH  64
#define HID 512
#define QKV_CH 1536
#define SCALE 0.125f   // 64^-0.5
#define GN_EPS 1e-5f

// Scratch (static device arrays: allocation-free rule)
__device__ float g_qkv[(size_t)B * QKV_CH * T];        // 402 MB
__device__ float g_y[(size_t)B * C * T];               // 134 MB
__device__ float g_ctx_part[(size_t)B * H * 8 * DH * DH]; // 16 MB
__device__ float g_ctx[(size_t)B * H * DH * DH];       // 2 MB
__device__ float g_weff[(size_t)B * C * C];            // 16 MB
__device__ float g_stats[B * 128 * 2];
__device__ float g_mr[B * 2];

// ------------------------- block reduce helpers ----------------------------
__device__ __forceinline__ float blockReduceSum(float v, float* sm) {
    __syncthreads();
    #pragma unroll
    for (int o = 16; o; o >>= 1) v += __shfl_down_sync(0xffffffffu, v, o);
    int lane = threadIdx.x & 31, w = threadIdx.x >> 5;
    if (lane == 0) sm[w] = v;
    __syncthreads();
    if (w == 0) {
        v = (lane < (int)(blockDim.x >> 5)) ? sm[lane] : 0.f;
        #pragma unroll
        for (int o = 16; o; o >>= 1) v += __shfl_down_sync(0xffffffffu, v, o);
        if (lane == 0) sm[0] = v;
    }
    __syncthreads();
    return sm[0];
}

__device__ __forceinline__ float blockReduceMax(float v, float* sm) {
    __syncthreads();
    #pragma unroll
    for (int o = 16; o; o >>= 1) v = fmaxf(v, __shfl_down_sync(0xffffffffu, v, o));
    int lane = threadIdx.x & 31, w = threadIdx.x >> 5;
    if (lane == 0) sm[w] = v;
    __syncthreads();
    if (w == 0) {
        v = (lane < (int)(blockDim.x >> 5)) ? sm[lane] : -1e30f;
        #pragma unroll
        for (int o = 16; o; o >>= 1) v = fmaxf(v, __shfl_down_sync(0xffffffffu, v, o));
        if (lane == 0) sm[0] = v;
    }
    __syncthreads();
    return sm[0];
}

// ------------------------- SGEMM: Y[b] = A[b] @ X[b] (+bias) ----------------
// A: [M,K] row-major (batch stride strideA; 0 = shared)
// X: [K,N] row-major at batch stride strideX
// Y: [M,N] row-major at batch stride strideY
#define BM 128
#define BN 128
#define BK 16
#define TM 8
#define TN 8

__global__ __launch_bounds__(256, 2)
void sgemm_wx(const float* __restrict__ A, long strideA,
              const float* __restrict__ X, long strideX,
              float* __restrict__ Y, long strideY,
              int M, int N, int K, const float* __restrict__ bias)
{
    __shared__ float As[BK][BM];
    __shared__ float Bs[BK][BN];

    const int b  = blockIdx.z;
    const float* Ab = A + (long)b * strideA;
    const float* Xb = X + (long)b * strideX;
    float*       Yb = Y + (long)b * strideY;
    const int bm = blockIdx.y * BM, bn = blockIdx.x * BN;
    const int tid = threadIdx.x;
    const int tx = tid & 15, ty = tid >> 4;

    float acc[TM][TN] = {};

    for (int k0 = 0; k0 < K; k0 += BK) {
        // A tile: 128 rows x 16 k  (vectorized along K, scattered transposed)
        #pragma unroll
        for (int i = 0; i < 2; i++) {
            int v = tid + i * 256;
            int row = v >> 2, c4 = (v & 3) * 4;
            float4 a = *(const float4*)&Ab[(long)(bm + row) * K + k0 + c4];
            As[c4 + 0][row] = a.x; As[c4 + 1][row] = a.y;
            As[c4 + 2][row] = a.z; As[c4 + 3][row] = a.w;
        }
        // B tile: 16 k x 128 n (vectorized along N)
        #pragma unroll
        for (int i = 0; i < 2; i++) {
            int v = tid + i * 256;
            int kr = v >> 5, c4 = (v & 31) * 4;
            *(float4*)&Bs[kr][c4] = *(const float4*)&Xb[(long)(k0 + kr) * N + bn + c4];
        }
        __syncthreads();

        #pragma unroll
        for (int k = 0; k < BK; k++) {
            float af[TM], bf[TN];
            *(float4*)&af[0] = *(const float4*)&As[k][ty * TM];
            *(float4*)&af[4] = *(const float4*)&As[k][ty * TM + 4];
            *(float4*)&bf[0] = *(const float4*)&Bs[k][tx * TN];
            *(float4*)&bf[4] = *(const float4*)&Bs[k][tx * TN + 4];
            #pragma unroll
            for (int i = 0; i < TM; i++)
                #pragma unroll
                for (int j = 0; j < TN; j++)
                    acc[i][j] = fmaf(af[i], bf[j], acc[i][j]);
        }
        __syncthreads();
    }

    #pragma unroll
    for (int i = 0; i < TM; i++) {
        int m = bm + ty * TM + i;
        float bv = bias ? bias[m] : 0.f;
        #pragma unroll
        for (int j = 0; j < TN; j += 4) {
            float4 o;
            o.x = acc[i][j + 0] + bv;
            o.y = acc[i][j + 1] + bv;
            o.z = acc[i][j + 2] + bv;
            o.w = acc[i][j + 3] + bv;
            *(float4*)&Yb[(long)m * N + bn + tx * TN + j] = o;
        }
    }
}

// --------------------- softmax over feature dim (q), *SCALE -----------------
// grid: (T/256, H, B), block 256; one thread per t
__global__ __launch_bounds__(256)
void softmax_q(float* __restrict__ qkv)
{
    int t = blockIdx.x * 256 + threadIdx.x;
    int h = blockIdx.y, b = blockIdx.z;
    float* base = qkv + (long)b * QKV_CH * T + (long)h * DH * T + t;

    float v[DH];
    float mx = -1e30f;
    #pragma unroll
    for (int d = 0; d < DH; d++) { v[d] = base[(long)d * T]; mx = fmaxf(mx, v[d]); }
    float s = 0.f;
    #pragma unroll
    for (int d = 0; d < DH; d++) { v[d] = __expf(v[d] - mx); s += v[d]; }
    float inv = SCALE / s;
    #pragma unroll
    for (int d = 0; d < DH; d++) base[(long)d * T] = v[d] * inv;
}

// --------------------- softmax over time dim (k) ----------------------------
// grid: B*512 rows, block 256; row = 4096 contiguous
__global__ __launch_bounds__(256)
void softmax_k(float* __restrict__ qkv)
{
    __shared__ float sm[32];
    int r = blockIdx.x;              // b*512 + c
    int b = r >> 9, c = r & 511;
    float* row = qkv + (long)b * QKV_CH * T + (long)(HID + c) * T;
    int tid = threadIdx.x;

    float v[16];
    float mx = -1e30f;
    #pragma unroll
    for (int i = 0; i < 16; i++) { v[i] = row[tid + i * 256]; mx = fmaxf(mx, v[i]); }
    mx = blockReduceMax(mx, sm);
    float s = 0.f;
    #pragma unroll
    for (int i = 0; i < 16; i++) { v[i] = __expf(v[i] - mx); s += v[i]; }
    s = blockReduceSum(s, sm);
    float inv = 1.f / s;
    #pragma unroll
    for (int i = 0; i < 16; i++) row[tid + i * 256] = v[i] * inv;
}

// --------------------- context partial: k @ v^T (split-K over t) ------------
// grid: (8 splits, B*H), block 256
__global__ __launch_bounds__(256)
void ctx_partial(const float* __restrict__ qkv, float* __restrict__ part)
{
    __shared__ float ks[32][65];
    __shared__ float vs[32][65];
    int s = blockIdx.x, bh = blockIdx.y;
    int b = bh >> 3, h = bh & 7;
    const float* kbase = qkv + (long)b * QKV_CH * T + (long)(HID + h * DH) * T;
    const float* vbase = qkv + (long)b * QKV_CH * T + (long)(2 * HID + h * DH) * T;
    int tid = threadIdx.x, tx = tid & 15, ty = tid >> 4;

    float acc[4][4] = {};
    for (int t0 = s * 512; t0 < s * 512 + 512; t0 += 32) {
        #pragma unroll
        for (int i = 0; i < 8; i++) {
            int v = tid + i * 256;
            int d = v >> 5, tl = v & 31;
            ks[tl][d] = kbase[(long)d * T + t0 + tl];
            vs[tl][d] = vbase[(long)d * T + t0 + tl];
        }
        __syncthreads();
        #pragma unroll
        for (int tl = 0; tl < 32; tl++) {
            float a[4], bb[4];
            #pragma unroll
            for (int i = 0; i < 4; i++) a[i]  = ks[tl][ty * 4 + i];
            #pragma unroll
            for (int j = 0; j < 4; j++) bb[j] = vs[tl][tx * 4 + j];
            #pragma unroll
            for (int i = 0; i < 4; i++)
                #pragma unroll
                for (int j = 0; j < 4; j++)
                    acc[i][j] = fmaf(a[i], bb[j], acc[i][j]);
        }
        __syncthreads();
    }
    float* p = part + ((long)bh * 8 + s) * (DH * DH);
    #pragma unroll
    for (int i = 0; i < 4; i++)
        #pragma unroll
        for (int j = 0; j < 4; j++)
            p[(ty * 4 + i) * DH + tx * 4 + j] = acc[i][j];
}

// grid: B*H, block 256
__global__ __launch_bounds__(256)
void ctx_reduce(const float* __restrict__ part, float* __restrict__ ctx)
{
    int bh = blockIdx.x;
    long base = (long)bh * 8 * (DH * DH);
    for (int i = threadIdx.x; i < DH * DH; i += 256) {
        float s = 0.f;
        #pragma unroll
        for (int sp = 0; sp < 8; sp++) s += part[base + (long)sp * (DH * DH) + i];
        ctx[(long)bh * (DH * DH) + i] = s;
    }
}

// ----- Weff[b][o][h*64+d] = sum_e Wout[o][h*64+e] * ctx[b][h][d][e] ---------
// grid: (B, H), block 256
__global__ __launch_bounds__(256)
void make_weff(const float* __restrict__ ctx, const float* __restrict__ Wout,
               float* __restrict__ weff)
{
    __shared__ float cs[DH][DH];   // ctx[d][e]
    int b = blockIdx.x, h = blockIdx.y;
    const float* c = ctx + (long)(b * H + h) * (DH * DH);
    for (int i = threadIdx.x; i < DH * DH; i += 256) cs[i >> 6][i & 63] = c[i];
    __syncthreads();

    #pragma unroll
    for (int oo = 0; oo < 2; oo++) {
        int o = threadIdx.x + oo * 256;
        float w[DH];
        #pragma unroll
        for (int e = 0; e < DH; e++) w[e] = Wout[(long)o * C + h * DH + e];
        for (int d = 0; d < DH; d++) {
            float s = 0.f;
            #pragma unroll
            for (int e = 0; e < DH; e++) s = fmaf(w[e], cs[d][e], s);
            weff[((long)b * C + o) * C + h * DH + d] = s;
        }
    }
}

// --------------------- GroupNorm ------------------------------------------
// grid: (128, B), block 256; each block reduces 16384 contiguous elems
__global__ __launch_bounds__(256)
void gn_stats(const float* __restrict__ y, float* __restrict__ stats)
{
    __shared__ float sm[32];
    int b = blockIdx.y, ch = blockIdx.x;
    const float* p = y + (long)b * C * T + (long)ch * 16384;
    float s = 0.f, ss = 0.f;
    for (int i = threadIdx.x * 4; i < 16384; i += 1024) {
        float4 v = *(const float4*)&p[i];
        s  += v.x + v.y + v.z + v.w;
        ss += v.x * v.x + v.y * v.y + v.z * v.z + v.w * v.w;
    }
    float S  = blockReduceSum(s, sm);
    float SS = blockReduceSum(ss, sm);
    if (threadIdx.x == 0) {
        stats[(b * 128 + ch) * 2 + 0] = S;
        stats[(b * 128 + ch) * 2 + 1] = SS;
    }
}

// grid: B, block 128
__global__ __launch_bounds__(128)
void gn_finalize(const float* __restrict__ stats, float* __restrict__ mr)
{
    __shared__ float sm[32];
    int b = blockIdx.x;
    float s  = stats[(b * 128 + threadIdx.x) * 2 + 0];
    float ss = stats[(b * 128 + threadIdx.x) * 2 + 1];
    float S  = blockReduceSum(s, sm);
    float SS = blockReduceSum(ss, sm);
    if (threadIdx.x == 0) {
        const float n = (float)((long)C * T);
        float mean = S / n;
        float var  = SS / n - mean * mean;
        mr[b * 2 + 0] = mean;
        mr[b * 2 + 1] = rsqrtf(var + GN_EPS);
    }
}

// grid: (C*T/1024, B), block 256, float4
__global__ __launch_bounds__(256)
void gn_norm(const float* __restrict__ y, const float* __restrict__ mr,
             const float* __restrict__ gw, const float* __restrict__ gb,
             float* __restrict__ out)
{
    int b = blockIdx.y;
    long base = (long)b * C * T;
    int idx = (blockIdx.x * 256 + threadIdx.x) * 4;
    int c = idx >> 12;                 // / 4096
    float mean = mr[b * 2 + 0], rstd = mr[b * 2 + 1];
    float g   = gw[c] * rstd;
    float beta = gb[c] - mean * g;
    float4 v = *(const float4*)&y[base + idx];
    v.x = fmaf(v.x, g, beta);
    v.y = fmaf(v.y, g, beta);
    v.z = fmaf(v.z, g, beta);
    v.w = fmaf(v.w, g, beta);
    *(float4*)&out[base + idx] = v;
}

// ---------------------------------------------------------------------------
extern "C" void kernel_launch(void* const* d_in, const int* in_sizes, int n_in,
                              void* d_out, int out_size)
{
    const float* x     = (const float*)d_in[0];
    const float* Wqkv  = (const float*)d_in[1];
    const float* Wout  = (const float*)d_in[2];
    const float* bout  = (const float*)d_in[3];
    const float* gnw   = (const float*)d_in[4];
    const float* gnb   = (const float*)d_in[5];
    float* out = (float*)d_out;

    float *qkv, *y, *part, *ctx, *weff, *stats, *mr;
    cudaGetSymbolAddress((void**)&qkv,   g_qkv);
    cudaGetSymbolAddress((void**)&y,     g_y);
    cudaGetSymbolAddress((void**)&part,  g_ctx_part);
    cudaGetSymbolAddress((void**)&ctx,   g_ctx);
    cudaGetSymbolAddress((void**)&weff,  g_weff);
    cudaGetSymbolAddress((void**)&stats, g_stats);
    cudaGetSymbolAddress((void**)&mr,    g_mr);

    // 1) qkv = Wqkv @ x            [1536x512] @ [512x4096] per batch
    sgemm_wx<<<dim3(T / BN, QKV_CH / BM, B), 256>>>(
        Wqkv, 0L, x, (long)C * T, qkv, (long)QKV_CH * T,
        QKV_CH, T, C, nullptr);

    // 2) softmaxes
    softmax_q<<<dim3(T / 256, H, B), 256>>>(qkv);
    softmax_k<<<B * HID, 256>>>(qkv);

    // 3) context = k @ v^T  (split-K 8) then reduce
    ctx_partial<<<dim3(8, B * H), 256>>>(qkv, part);
    ctx_reduce<<<B * H, 256>>>(part, ctx);

    // 4) fold Wout with context
    make_weff<<<dim3(B, H), 256>>>(ctx, Wout, weff);

    // 5) y = Weff @ q + b_out      [512x512] @ [512x4096] per batch
    sgemm_wx<<<dim3(T / BN, C / BM, B), 256>>>(
        weff, (long)C * C, qkv, (long)QKV_CH * T, y, (long)C * T,
        C, T, C, bout);

    // 6) GroupNorm
    gn_stats<<<dim3(128, B), 256>>>(y, stats);
    gn_finalize<<<B, 128>>>(stats, mr);
    gn_norm<<<dim3((C * T) / 1024, B), 256>>>(y, mr, gnw, gnb, out);
}

// round 5
// speedup vs baseline: 2.5307x; 2.5307x over previous
#include <cuda_runtime.h>
#include <cuda_bf16.h>
#include <cstdint>

// ---------------------------------------------------------------------------
// LinearAttention: qkv = Wqkv@x ; q=softmax_d(q)*scale ; k=softmax_t(k)
// ctx = k@v^T (64x64 per b,h) ; Weff = Wout*ctx fold ; y = Weff@q + b_out
// GroupNorm(1) over (c,t) per batch.
// b=16, c=512, t=4096, heads=8, dh=64, hidden=512
// GEMMs: mma.sync tf32 (HMMA; tcgen05 unavailable: harness PTX targets
// plain compute_103). cp.async double-buffered, cvt.rna at fragment load.
// ---------------------------------------------------------------------------

#define B   16
#define C   512
#define T   4096
#define H   8
#define DH  64
#define HID 512
#define QKV_CH 1536
#define SCALE 0.125f   // 64^-0.5
#define GN_EPS 1e-5f

// Scratch (static device arrays: allocation-free rule)
__device__ float g_qkv[(size_t)B * QKV_CH * T];        // 402 MB
__device__ float g_y[(size_t)B * C * T];               // 134 MB
__device__ float g_ctx_part[(size_t)B * H * 8 * DH * DH]; // 16 MB
__device__ float g_ctx[(size_t)B * H * DH * DH];       // 2 MB
__device__ float g_weff[(size_t)B * C * C];            // 16 MB
__device__ float g_stats[B * 128 * 2];
__device__ float g_mr[B * 2];

// ========================= helpers =========================================
__device__ __forceinline__ uint32_t smem_u32(const void* p) {
    uint32_t a;
    asm("{ .reg .u64 t; cvta.to.shared.u64 t, %1; cvt.u32.u64 %0, t; }"
        : "=r"(a) : "l"(p));
    return a;
}

__device__ __forceinline__ uint32_t f2tf(float f) {
    uint32_t r;
    asm("cvt.rna.tf32.f32 %0, %1;" : "=r"(r) : "f"(f));
    return r;
}

__device__ __forceinline__ void cp_async16(uint32_t smem_dst, const void* gsrc) {
    asm volatile("cp.async.cg.shared.global [%0], [%1], 16;"
                 :: "r"(smem_dst), "l"(gsrc));
}
__device__ __forceinline__ void cp_commit() {
    asm volatile("cp.async.commit_group;" ::: "memory");
}
template <int N>
__device__ __forceinline__ void cp_wait() {
    asm volatile("cp.async.wait_group %0;" :: "n"(N) : "memory");
}

__device__ __forceinline__ void mma16n8k8(float* c, const uint32_t* a,
                                          const uint32_t* b) {
    asm volatile(
        "mma.sync.aligned.m16n8k8.row.col.f32.tf32.tf32.f32 "
        "{%0,%1,%2,%3}, {%4,%5,%6,%7}, {%8,%9}, {%0,%1,%2,%3};"
        : "+f"(c[0]), "+f"(c[1]), "+f"(c[2]), "+f"(c[3])
        : "r"(a[0]), "r"(a[1]), "r"(a[2]), "r"(a[3]),
          "r"(b[0]), "r"(b[1]));
}

// ========================= tf32 HMMA GEMM ==================================
// Y[b][M,N] = A[b][M,K] @ X[b][K,N] (+bias[m])
// A row-major, X row-major. Tile 128x128x32, 8 warps (2m x 4n), 2-stage cp.async.
#define BM 128
#define BN 128
#define BK 32
#define AS_STRIDE 36      // floats per A row (pad 4) -> frag LDS conflict-free
#define BS_STRIDE 132     // floats per B row (pad 4) -> frag LDS conflict-free
#define AS_BYTES (BM * AS_STRIDE * 4)   // 18432
#define BS_BYTES (BK * BS_STRIDE * 4)   // 16896
#define STAGE_BYTES (AS_BYTES + BS_BYTES)
#define TGEMM_SMEM (2 * STAGE_BYTES)    // 70656

__global__ __launch_bounds__(256)
void tgemm_tf32(const float* __restrict__ A, long strideA,
                const float* __restrict__ X, long strideX,
                float* __restrict__ Y, long strideY,
                int M, int N, int K, const float* __restrict__ bias)
{
    extern __shared__ char dsm[];
    const int tid = threadIdx.x;
    const int wid = tid >> 5;
    const int lane = tid & 31;
    const int b  = blockIdx.z;
    const int bm = blockIdx.y * BM, bn = blockIdx.x * BN;
    const float* Ab = A + (long)b * strideA + (long)bm * K;
    const float* Xb = X + (long)b * strideX + bn;

    const uint32_t smem0 = smem_u32(dsm);

    // precomputed cp.async targets (element offsets within a stage)
    // A: chunk v = tid + i*256 -> row=v>>3, k4=(v&7)*4
    // B: chunk v = tid + i*256 -> kr=v>>5, n4=(v&31)*4
    uint32_t a_dst[4], b_dst[4];
    int a_row[4], a_k4[4], b_kr[4], b_n4[4];
    #pragma unroll
    for (int i = 0; i < 4; i++) {
        int v = tid + i * 256;
        a_row[i] = v >> 3; a_k4[i] = (v & 7) * 4;
        b_kr[i]  = v >> 5; b_n4[i] = (v & 31) * 4;
        a_dst[i] = (uint32_t)(a_row[i] * AS_STRIDE + a_k4[i]) * 4u;
        b_dst[i] = (uint32_t)(AS_BYTES + (b_kr[i] * BS_STRIDE + b_n4[i]) * 4u);
    }

    const int warpM = (wid >> 2) * 64;
    const int warpN = (wid & 3) * 32;

    float acc[4][4][4];
    #pragma unroll
    for (int mt = 0; mt < 4; mt++)
        #pragma unroll
        for (int nt = 0; nt < 4; nt++)
            #pragma unroll
            for (int r = 0; r < 4; r++) acc[mt][nt][r] = 0.f;

    const int niter = K / BK;   // 16

    // prologue: stage 0
    {
        const int k0 = 0;
        const uint32_t sb = smem0;
        #pragma unroll
        for (int i = 0; i < 4; i++)
            cp_async16(sb + a_dst[i], &Ab[(long)a_row[i] * K + k0 + a_k4[i]]);
        #pragma unroll
        for (int i = 0; i < 4; i++)
            cp_async16(sb + b_dst[i], &Xb[(long)(k0 + b_kr[i]) * N + b_n4[i]]);
        cp_commit();
    }

    for (int it = 0; it < niter; it++) {
        if (it + 1 < niter) {
            const int k0 = (it + 1) * BK;
            const uint32_t sb = smem0 + ((it + 1) & 1) * STAGE_BYTES;
            #pragma unroll
            for (int i = 0; i < 4; i++)
                cp_async16(sb + a_dst[i], &Ab[(long)a_row[i] * K + k0 + a_k4[i]]);
            #pragma unroll
            for (int i = 0; i < 4; i++)
                cp_async16(sb + b_dst[i], &Xb[(long)(k0 + b_kr[i]) * N + b_n4[i]]);
            cp_commit();
            cp_wait<1>();
        } else {
            cp_wait<0>();
        }
        __syncthreads();

        const float* As = (const float*)(dsm + (it & 1) * STAGE_BYTES);
        const float* Bs = (const float*)(dsm + (it & 1) * STAGE_BYTES + AS_BYTES);

        #pragma unroll
        for (int kk = 0; kk < 4; kk++) {
            const int kb = kk * 8 + (lane & 3);
            // B fragments
            uint32_t bfr[4][2];
            #pragma unroll
            for (int nt = 0; nt < 4; nt++) {
                int n = warpN + nt * 8 + (lane >> 2);
                bfr[nt][0] = f2tf(Bs[kb * BS_STRIDE + n]);
                bfr[nt][1] = f2tf(Bs[(kb + 4) * BS_STRIDE + n]);
            }
            // A fragments
            uint32_t afr[4][4];
            #pragma unroll
            for (int mt = 0; mt < 4; mt++) {
                int m = warpM + mt * 16 + (lane >> 2);
                afr[mt][0] = f2tf(As[m * AS_STRIDE + kb]);
                afr[mt][1] = f2tf(As[(m + 8) * AS_STRIDE + kb]);
                afr[mt][2] = f2tf(As[m * AS_STRIDE + kb + 4]);
                afr[mt][3] = f2tf(As[(m + 8) * AS_STRIDE + kb + 4]);
            }
            #pragma unroll
            for (int mt = 0; mt < 4; mt++)
                #pragma unroll
                for (int nt = 0; nt < 4; nt++)
                    mma16n8k8(acc[mt][nt], afr[mt], bfr[nt]);
        }
        __syncthreads();
    }

    // epilogue: c0:(g, t*2) c1:(g, t*2+1) c2:(g+8, t*2) c3:(g+8, t*2+1)
    float* Yb = Y + (long)b * strideY;
    #pragma unroll
    for (int mt = 0; mt < 4; mt++) {
        int row0 = bm + warpM + mt * 16 + (lane >> 2);
        float bv0 = bias ? bias[row0] : 0.f;
        float bv1 = bias ? bias[row0 + 8] : 0.f;
        #pragma unroll
        for (int nt = 0; nt < 4; nt++) {
            int col = bn + warpN + nt * 8 + (lane & 3) * 2;
            float2 o0, o1;
            o0.x = acc[mt][nt][0] + bv0; o0.y = acc[mt][nt][1] + bv0;
            o1.x = acc[mt][nt][2] + bv1; o1.y = acc[mt][nt][3] + bv1;
            *(float2*)&Yb[(long)row0 * N + col] = o0;
            *(float2*)&Yb[(long)(row0 + 8) * N + col] = o1;
        }
    }
}

// ------------------------- block reduce helpers ----------------------------
__device__ __forceinline__ float blockReduceSum(float v, float* sm) {
    __syncthreads();
    #pragma unroll
    for (int o = 16; o; o >>= 1) v += __shfl_down_sync(0xffffffffu, v, o);
    int lane = threadIdx.x & 31, w = threadIdx.x >> 5;
    if (lane == 0) sm[w] = v;
    __syncthreads();
    if (w == 0) {
        v = (lane < (int)(blockDim.x >> 5)) ? sm[lane] : 0.f;
        #pragma unroll
        for (int o = 16; o; o >>= 1) v += __shfl_down_sync(0xffffffffu, v, o);
        if (lane == 0) sm[0] = v;
    }
    __syncthreads();
    return sm[0];
}

__device__ __forceinline__ float blockReduceMax(float v, float* sm) {
    __syncthreads();
    #pragma unroll
    for (int o = 16; o; o >>= 1) v = fmaxf(v, __shfl_down_sync(0xffffffffu, v, o));
    int lane = threadIdx.x & 31, w = threadIdx.x >> 5;
    if (lane == 0) sm[w] = v;
    __syncthreads();
    if (w == 0) {
        v = (lane < (int)(blockDim.x >> 5)) ? sm[lane] : -1e30f;
        #pragma unroll
        for (int o = 16; o; o >>= 1) v = fmaxf(v, __shfl_down_sync(0xffffffffu, v, o));
        if (lane == 0) sm[0] = v;
    }
    __syncthreads();
    return sm[0];
}

// --------------------- softmax over feature dim (q), *SCALE -----------------
__global__ __launch_bounds__(256)
void softmax_q(float* __restrict__ qkv)
{
    int t = blockIdx.x * 256 + threadIdx.x;
    int h = blockIdx.y, b = blockIdx.z;
    float* base = qkv + (long)b * QKV_CH * T + (long)h * DH * T + t;

    float v[DH];
    float mx = -1e30f;
    #pragma unroll
    for (int d = 0; d < DH; d++) { v[d] = base[(long)d * T]; mx = fmaxf(mx, v[d]); }
    float s = 0.f;
    #pragma unroll
    for (int d = 0; d < DH; d++) { v[d] = __expf(v[d] - mx); s += v[d]; }
    float inv = SCALE / s;
    #pragma unroll
    for (int d = 0; d < DH; d++) base[(long)d * T] = v[d] * inv;
}

// --------------------- softmax over time dim (k) ----------------------------
__global__ __launch_bounds__(256)
void softmax_k(float* __restrict__ qkv)
{
    __shared__ float sm[32];
    int r = blockIdx.x;              // b*512 + c
    int b = r >> 9, c = r & 511;
    float* row = qkv + (long)b * QKV_CH * T + (long)(HID + c) * T;
    int tid = threadIdx.x;

    float v[16];
    float mx = -1e30f;
    #pragma unroll
    for (int i = 0; i < 16; i++) { v[i] = row[tid + i * 256]; mx = fmaxf(mx, v[i]); }
    mx = blockReduceMax(mx, sm);
    float s = 0.f;
    #pragma unroll
    for (int i = 0; i < 16; i++) { v[i] = __expf(v[i] - mx); s += v[i]; }
    s = blockReduceSum(s, sm);
    float inv = 1.f / s;
    #pragma unroll
    for (int i = 0; i < 16; i++) row[tid + i * 256] = v[i] * inv;
}

// --------------------- context partial: k @ v^T (split-K over t) ------------
__global__ __launch_bounds__(256)
void ctx_partial(const float* __restrict__ qkv, float* __restrict__ part)
{
    __shared__ float ks[32][65];
    __shared__ float vs[32][65];
    int s = blockIdx.x, bh = blockIdx.y;
    int b = bh >> 3, h = bh & 7;
    const float* kbase = qkv + (long)b * QKV_CH * T + (long)(HID + h * DH) * T;
    const float* vbase = qkv + (long)b * QKV_CH * T + (long)(2 * HID + h * DH) * T;
    int tid = threadIdx.x, tx = tid & 15, ty = tid >> 4;

    float acc[4][4] = {};
    for (int t0 = s * 512; t0 < s * 512 + 512; t0 += 32) {
        #pragma unroll
        for (int i = 0; i < 8; i++) {
            int v = tid + i * 256;
            int d = v >> 5, tl = v & 31;
            ks[tl][d] = kbase[(long)d * T + t0 + tl];
            vs[tl][d] = vbase[(long)d * T + t0 + tl];
        }
        __syncthreads();
        #pragma unroll
        for (int tl = 0; tl < 32; tl++) {
            float a[4], bb[4];
            #pragma unroll
            for (int i = 0; i < 4; i++) a[i]  = ks[tl][ty * 4 + i];
            #pragma unroll
            for (int j = 0; j < 4; j++) bb[j] = vs[tl][tx * 4 + j];
            #pragma unroll
            for (int i = 0; i < 4; i++)
                #pragma unroll
                for (int j = 0; j < 4; j++)
                    acc[i][j] = fmaf(a[i], bb[j], acc[i][j]);
        }
        __syncthreads();
    }
    float* p = part + ((long)bh * 8 + s) * (DH * DH);
    #pragma unroll
    for (int i = 0; i < 4; i++)
        #pragma unroll
        for (int j = 0; j < 4; j++)
            p[(ty * 4 + i) * DH + tx * 4 + j] = acc[i][j];
}

__global__ __launch_bounds__(256)
void ctx_reduce(const float* __restrict__ part, float* __restrict__ ctx)
{
    int bh = blockIdx.x;
    long base = (long)bh * 8 * (DH * DH);
    for (int i = threadIdx.x; i < DH * DH; i += 256) {
        float s = 0.f;
        #pragma unroll
        for (int sp = 0; sp < 8; sp++) s += part[base + (long)sp * (DH * DH) + i];
        ctx[(long)bh * (DH * DH) + i] = s;
    }
}

// ----- Weff[b][o][h*64+d] = sum_e Wout[o][h*64+e] * ctx[b][h][d][e] ---------
__global__ __launch_bounds__(256)
void make_weff(const float* __restrict__ ctx, const float* __restrict__ Wout,
               float* __restrict__ weff)
{
    __shared__ float cs[DH][DH];   // ctx[d][e]
    int b = blockIdx.x, h = blockIdx.y;
    const float* c = ctx + (long)(b * H + h) * (DH * DH);
    for (int i = threadIdx.x; i < DH * DH; i += 256) cs[i >> 6][i & 63] = c[i];
    __syncthreads();

    #pragma unroll
    for (int oo = 0; oo < 2; oo++) {
        int o = threadIdx.x + oo * 256;
        float w[DH];
        #pragma unroll
        for (int e = 0; e < DH; e++) w[e] = Wout[(long)o * C + h * DH + e];
        for (int d = 0; d < DH; d++) {
            float s = 0.f;
            #pragma unroll
            for (int e = 0; e < DH; e++) s = fmaf(w[e], cs[d][e], s);
            weff[((long)b * C + o) * C + h * DH + d] = s;
        }
    }
}

// --------------------- GroupNorm ------------------------------------------
__global__ __launch_bounds__(256)
void gn_stats(const float* __restrict__ y, float* __restrict__ stats)
{
    __shared__ float sm[32];
    int b = blockIdx.y, ch = blockIdx.x;
    const float* p = y + (long)b * C * T + (long)ch * 16384;
    float s = 0.f, ss = 0.f;
    for (int i = threadIdx.x * 4; i < 16384; i += 1024) {
        float4 v = *(const float4*)&p[i];
        s  += v.x + v.y + v.z + v.w;
        ss += v.x * v.x + v.y * v.y + v.z * v.z + v.w * v.w;
    }
    float S  = blockReduceSum(s, sm);
    float SS = blockReduceSum(ss, sm);
    if (threadIdx.x == 0) {
        stats[(b * 128 + ch) * 2 + 0] = S;
        stats[(b * 128 + ch) * 2 + 1] = SS;
    }
}

__global__ __launch_bounds__(128)
void gn_finalize(const float* __restrict__ stats, float* __restrict__ mr)
{
    __shared__ float sm[32];
    int b = blockIdx.x;
    float s  = stats[(b * 128 + threadIdx.x) * 2 + 0];
    float ss = stats[(b * 128 + threadIdx.x) * 2 + 1];
    float S  = blockReduceSum(s, sm);
    float SS = blockReduceSum(ss, sm);
    if (threadIdx.x == 0) {
        const float n = (float)((long)C * T);
        float mean = S / n;
        float var  = SS / n - mean * mean;
        mr[b * 2 + 0] = mean;
        mr[b * 2 + 1] = rsqrtf(var + GN_EPS);
    }
}

__global__ __launch_bounds__(256)
void gn_norm(const float* __restrict__ y, const float* __restrict__ mr,
             const float* __restrict__ gw, const float* __restrict__ gb,
             float* __restrict__ out)
{
    int b = blockIdx.y;
    long base = (long)b * C * T;
    int idx = (blockIdx.x * 256 + threadIdx.x) * 4;
    int c = idx >> 12;                 // / 4096
    float mean = mr[b * 2 + 0], rstd = mr[b * 2 + 1];
    float g   = gw[c] * rstd;
    float beta = gb[c] - mean * g;
    float4 v = *(const float4*)&y[base + idx];
    v.x = fmaf(v.x, g, beta);
    v.y = fmaf(v.y, g, beta);
    v.z = fmaf(v.z, g, beta);
    v.w = fmaf(v.w, g, beta);
    *(float4*)&out[base + idx] = v;
}

// ---------------------------------------------------------------------------
extern "C" void kernel_launch(void* const* d_in, const int* in_sizes, int n_in,
                              void* d_out, int out_size)
{
    const float* x     = (const float*)d_in[0];
    const float* Wqkv  = (const float*)d_in[1];
    const float* Wout  = (const float*)d_in[2];
    const float* bout  = (const float*)d_in[3];
    const float* gnw   = (const float*)d_in[4];
    const float* gnb   = (const float*)d_in[5];
    float* out = (float*)d_out;

    float *qkv, *y, *part, *ctx, *weff, *stats, *mr;
    cudaGetSymbolAddress((void**)&qkv,   g_qkv);
    cudaGetSymbolAddress((void**)&y,     g_y);
    cudaGetSymbolAddress((void**)&part,  g_ctx_part);
    cudaGetSymbolAddress((void**)&ctx,   g_ctx);
    cudaGetSymbolAddress((void**)&weff,  g_weff);
    cudaGetSymbolAddress((void**)&stats, g_stats);
    cudaGetSymbolAddress((void**)&mr,    g_mr);

    cudaFuncSetAttribute(tgemm_tf32,
                         cudaFuncAttributeMaxDynamicSharedMemorySize, TGEMM_SMEM);

    // 1) qkv = Wqkv @ x            [1536x512] @ [512x4096] per batch
    tgemm_tf32<<<dim3(T / BN, QKV_CH / BM, B), 256, TGEMM_SMEM>>>(
        Wqkv, 0L, x, (long)C * T, qkv, (long)QKV_CH * T,
        QKV_CH, T, C, nullptr);

    // 2) softmaxes
    softmax_q<<<dim3(T / 256, H, B), 256>>>(qkv);
    softmax_k<<<B * HID, 256>>>(qkv);

    // 3) context = k @ v^T  (split-K 8) then reduce
    ctx_partial<<<dim3(8, B * H), 256>>>(qkv, part);
    ctx_reduce<<<B * H, 256>>>(part, ctx);

    // 4) fold Wout with context
    make_weff<<<dim3(B, H), 256>>>(ctx, Wout, weff);

    // 5) y = Weff @ q + b_out      [512x512] @ [512x4096] per batch
    tgemm_tf32<<<dim3(T / BN, C / BM, B), 256, TGEMM_SMEM>>>(
        weff, (long)C * C, qkv, (long)QKV_CH * T, y, (long)C * T,
        C, T, C, bout);

    // 6) GroupNorm
    gn_stats<<<dim3(128, B), 256>>>(y, stats);
    gn_finalize<<<B, 128>>>(stats, mr);
    gn_norm<<<dim3((C * T) / 1024, B), 256>>>(y, mr, gnw, gnb, out);
}

// round 6
// speedup vs baseline: 2.6020x; 1.0282x over previous
#include <cuda_runtime.h>
#include <cuda_bf16.h>
#include <cstdint>

// ---------------------------------------------------------------------------
// LinearAttention: qkv = Wqkv@x ; q=softmax_d(q)*scale ; k=softmax_t(k)
// ctx = k@v^T (64x64 per b,h) ; Weff = Wout*ctx fold ; y = Weff@q + b_out
// GroupNorm(1) over (c,t) per batch.
// b=16, c=512, t=4096, heads=8, dh=64, hidden=512
// GEMMs: mma.sync tf32 HMMA, 128x256x32 tiles, 64x64/warp, 3-stage cp.async.
// Inputs pre-rounded to tf32 (rna) at producers -> no inner-loop CVT.
// ---------------------------------------------------------------------------

#define B   16
#define C   512
#define T   4096
#define H   8
#define DH  64
#define HID 512
#define QKV_CH 1536
#define SCALE 0.125f   // 64^-0.5
#define GN_EPS 1e-5f

// Scratch (static device arrays: allocation-free rule)
__device__ float g_qkv[(size_t)B * QKV_CH * T];        // 402 MB
__device__ float g_y[(size_t)B * C * T];               // 134 MB (also xr scratch)
__device__ float g_ctx_part[(size_t)B * H * 8 * DH * DH]; // 16 MB
__device__ float g_ctx[(size_t)B * H * DH * DH];       // 2 MB
__device__ float g_weff[(size_t)B * C * C];            // 16 MB (also Wqkv_r scratch)
__device__ float g_stats[B * 128 * 2];
__device__ float g_mr[B * 2];

// ========================= helpers =========================================
__device__ __forceinline__ uint32_t smem_u32(const void* p) {
    uint32_t a;
    asm("{ .reg .u64 t; cvta.to.shared.u64 t, %1; cvt.u32.u64 %0, t; }"
        : "=r"(a) : "l"(p));
    return a;
}

__device__ __forceinline__ float f2tf_f(float f) {
    uint32_t r;
    asm("cvt.rna.tf32.f32 %0, %1;" : "=r"(r) : "f"(f));
    return __uint_as_float(r);
}

__device__ __forceinline__ void cp_async16(uint32_t smem_dst, const void* gsrc) {
    asm volatile("cp.async.cg.shared.global [%0], [%1], 16;"
                 :: "r"(smem_dst), "l"(gsrc));
}
__device__ __forceinline__ void cp_commit() {
    asm volatile("cp.async.commit_group;" ::: "memory");
}
template <int N>
__device__ __forceinline__ void cp_wait() {
    asm volatile("cp.async.wait_group %0;" :: "n"(N) : "memory");
}

__device__ __forceinline__ void mma16n8k8(float* c, const uint32_t* a,
                                          const uint32_t* b) {
    asm volatile(
        "mma.sync.aligned.m16n8k8.row.col.f32.tf32.tf32.f32 "
        "{%0,%1,%2,%3}, {%4,%5,%6,%7}, {%8,%9}, {%0,%1,%2,%3};"
        : "+f"(c[0]), "+f"(c[1]), "+f"(c[2]), "+f"(c[3])
        : "r"(a[0]), "r"(a[1]), "r"(a[2]), "r"(a[3]),
          "r"(b[0]), "r"(b[1]));
}

// ========================= tf32 HMMA GEMM ==================================
// Y[b][M,N] = A[b][M,K] @ X[b][K,N] (+bias[m]) ; inputs pre-rounded to tf32.
// Tile 128x256x32, 8 warps (2m x 4n) of 64x64, 3-stage cp.async.
#define BM 128
#define BN 256
#define BK 32
#define AS_STRIDE 36      // A row pad: bank (4m+k)%32 distinct
#define BS_STRIDE 264     // B row pad: bank (8k+n)%32 distinct
#define AS_BYTES (BM * AS_STRIDE * 4)   // 18432
#define BS_BYTES (BK * BS_STRIDE * 4)   // 33792
#define STAGE_BYTES (AS_BYTES + BS_BYTES)  // 52224
#define NSTAGE 3
#define TGEMM_SMEM (NSTAGE * STAGE_BYTES)  // 156672

__global__ __launch_bounds__(256, 1)
void tgemm_tf32(const float* __restrict__ A, long strideA,
                const float* __restrict__ X, long strideX,
                float* __restrict__ Y, long strideY,
                int M, int N, int K, const float* __restrict__ bias)
{
    extern __shared__ char dsm[];
    const int tid = threadIdx.x;
    const int wid = tid >> 5;
    const int lane = tid & 31;
    const int gid = lane >> 2;      // group (0..7)
    const int tg  = lane & 3;       // thread-in-group
    const int b  = blockIdx.z;
    const int bm = blockIdx.y * BM, bn = blockIdx.x * BN;
    const float* Ab = A + (long)b * strideA + (long)bm * K;
    const float* Xb = X + (long)b * strideX + bn;

    const uint32_t smem0 = smem_u32(dsm);

    const int warpM = (wid >> 2) * 64;
    const int warpN = (wid & 3) * 64;

    float acc[4][8][4];
    #pragma unroll
    for (int mt = 0; mt < 4; mt++)
        #pragma unroll
        for (int nt = 0; nt < 8; nt++)
            #pragma unroll
            for (int r = 0; r < 4; r++) acc[mt][nt][r] = 0.f;

    const int niter = K / BK;   // 16

    // stage loader: A 4 chunks/thread, B 8 chunks/thread
    auto load_stage = [&](int it) {
        const int k0 = it * BK;
        const uint32_t sb = smem0 + (it % NSTAGE) * STAGE_BYTES;
        #pragma unroll
        for (int i = 0; i < 4; i++) {
            int v = tid + i * 256;
            int row = v >> 3, k4 = (v & 7) * 4;
            cp_async16(sb + (uint32_t)(row * AS_STRIDE + k4) * 4u,
                       &Ab[(long)row * K + k0 + k4]);
        }
        #pragma unroll
        for (int i = 0; i < 8; i++) {
            int v = tid + i * 256;
            int kr = v >> 6, n4 = (v & 63) * 4;
            cp_async16(sb + (uint32_t)AS_BYTES + (uint32_t)(kr * BS_STRIDE + n4) * 4u,
                       &Xb[(long)(k0 + kr) * N + n4]);
        }
        cp_commit();
    };

    load_stage(0);
    load_stage(1);

    for (int it = 0; it < niter; it++) {
        if (it + 2 < niter) { load_stage(it + 2); cp_wait<2>(); }
        else if (it + 1 < niter) { cp_wait<1>(); }
        else { cp_wait<0>(); }
        __syncthreads();

        const uint32_t* As = (const uint32_t*)(dsm + (it % NSTAGE) * STAGE_BYTES);
        const uint32_t* Bs = (const uint32_t*)(dsm + (it % NSTAGE) * STAGE_BYTES + AS_BYTES);

        #pragma unroll
        for (int kk = 0; kk < 4; kk++) {
            const int kb = kk * 8 + tg;
            uint32_t bfr[8][2];
            #pragma unroll
            for (int nt = 0; nt < 8; nt++) {
                int n = warpN + nt * 8 + gid;
                bfr[nt][0] = Bs[kb * BS_STRIDE + n];
                bfr[nt][1] = Bs[(kb + 4) * BS_STRIDE + n];
            }
            uint32_t afr[4][4];
            #pragma unroll
            for (int mt = 0; mt < 4; mt++) {
                int m = warpM + mt * 16 + gid;
                afr[mt][0] = As[m * AS_STRIDE + kb];
                afr[mt][1] = As[(m + 8) * AS_STRIDE + kb];
                afr[mt][2] = As[m * AS_STRIDE + kb + 4];
                afr[mt][3] = As[(m + 8) * AS_STRIDE + kb + 4];
            }
            #pragma unroll
            for (int mt = 0; mt < 4; mt++)
                #pragma unroll
                for (int nt = 0; nt < 8; nt++)
                    mma16n8k8(acc[mt][nt], afr[mt], bfr[nt]);
        }
        __syncthreads();
    }

    // epilogue
    float* Yb = Y + (long)b * strideY;
    #pragma unroll
    for (int mt = 0; mt < 4; mt++) {
        int row0 = bm + warpM + mt * 16 + gid;
        float bv0 = bias ? bias[row0] : 0.f;
        float bv1 = bias ? bias[row0 + 8] : 0.f;
        #pragma unroll
        for (int nt = 0; nt < 8; nt++) {
            int col = bn + warpN + nt * 8 + tg * 2;
            float2 o0, o1;
            o0.x = acc[mt][nt][0] + bv0; o0.y = acc[mt][nt][1] + bv0;
            o1.x = acc[mt][nt][2] + bv1; o1.y = acc[mt][nt][3] + bv1;
            *(float2*)&Yb[(long)row0 * N + col] = o0;
            *(float2*)&Yb[(long)(row0 + 8) * N + col] = o1;
        }
    }
}

// --------------------- tf32 pre-round pass ---------------------------------
__global__ __launch_bounds__(256)
void round_tf32(const float* __restrict__ in, float* __restrict__ out, int n4)
{
    int i = blockIdx.x * 256 + threadIdx.x;
    if (i >= n4) return;
    float4 v = ((const float4*)in)[i];
    v.x = f2tf_f(v.x); v.y = f2tf_f(v.y);
    v.z = f2tf_f(v.z); v.w = f2tf_f(v.w);
    ((float4*)out)[i] = v;
}

// ------------------------- block reduce helpers ----------------------------
__device__ __forceinline__ float blockReduceSum(float v, float* sm) {
    __syncthreads();
    #pragma unroll
    for (int o = 16; o; o >>= 1) v += __shfl_down_sync(0xffffffffu, v, o);
    int lane = threadIdx.x & 31, w = threadIdx.x >> 5;
    if (lane == 0) sm[w] = v;
    __syncthreads();
    if (w == 0) {
        v = (lane < (int)(blockDim.x >> 5)) ? sm[lane] : 0.f;
        #pragma unroll
        for (int o = 16; o; o >>= 1) v += __shfl_down_sync(0xffffffffu, v, o);
        if (lane == 0) sm[0] = v;
    }
    __syncthreads();
    return sm[0];
}

__device__ __forceinline__ float blockReduceMax(float v, float* sm) {
    __syncthreads();
    #pragma unroll
    for (int o = 16; o; o >>= 1) v = fmaxf(v, __shfl_down_sync(0xffffffffu, v, o));
    int lane = threadIdx.x & 31, w = threadIdx.x >> 5;
    if (lane == 0) sm[w] = v;
    __syncthreads();
    if (w == 0) {
        v = (lane < (int)(blockDim.x >> 5)) ? sm[lane] : -1e30f;
        #pragma unroll
        for (int o = 16; o; o >>= 1) v = fmaxf(v, __shfl_down_sync(0xffffffffu, v, o));
        if (lane == 0) sm[0] = v;
    }
    __syncthreads();
    return sm[0];
}

// --------------------- softmax over feature dim (q), *SCALE, tf32-round ----
__global__ __launch_bounds__(256)
void softmax_q(float* __restrict__ qkv)
{
    int t = blockIdx.x * 256 + threadIdx.x;
    int h = blockIdx.y, b = blockIdx.z;
    float* base = qkv + (long)b * QKV_CH * T + (long)h * DH * T + t;

    float v[DH];
    float mx = -1e30f;
    #pragma unroll
    for (int d = 0; d < DH; d++) { v[d] = base[(long)d * T]; mx = fmaxf(mx, v[d]); }
    float s = 0.f;
    #pragma unroll
    for (int d = 0; d < DH; d++) { v[d] = __expf(v[d] - mx); s += v[d]; }
    float inv = SCALE / s;
    #pragma unroll
    for (int d = 0; d < DH; d++) base[(long)d * T] = f2tf_f(v[d] * inv);
}

// --------------------- softmax over time dim (k) ----------------------------
__global__ __launch_bounds__(256)
void softmax_k(float* __restrict__ qkv)
{
    __shared__ float sm[32];
    int r = blockIdx.x;              // b*512 + c
    int b = r >> 9, c = r & 511;
    float* row = qkv + (long)b * QKV_CH * T + (long)(HID + c) * T;
    int tid = threadIdx.x;

    float v[16];
    float mx = -1e30f;
    #pragma unroll
    for (int i = 0; i < 16; i++) { v[i] = row[tid + i * 256]; mx = fmaxf(mx, v[i]); }
    mx = blockReduceMax(mx, sm);
    float s = 0.f;
    #pragma unroll
    for (int i = 0; i < 16; i++) { v[i] = __expf(v[i] - mx); s += v[i]; }
    s = blockReduceSum(s, sm);
    float inv = 1.f / s;
    #pragma unroll
    for (int i = 0; i < 16; i++) row[tid + i * 256] = v[i] * inv;
}

// --------------------- context partial: k @ v^T (split-K over t) ------------
__global__ __launch_bounds__(256)
void ctx_partial(const float* __restrict__ qkv, float* __restrict__ part)
{
    __shared__ float ks[32][65];
    __shared__ float vs[32][65];
    int s = blockIdx.x, bh = blockIdx.y;
    int b = bh >> 3, h = bh & 7;
    const float* kbase = qkv + (long)b * QKV_CH * T + (long)(HID + h * DH) * T;
    const float* vbase = qkv + (long)b * QKV_CH * T + (long)(2 * HID + h * DH) * T;
    int tid = threadIdx.x, tx = tid & 15, ty = tid >> 4;

    float acc[4][4] = {};
    for (int t0 = s * 512; t0 < s * 512 + 512; t0 += 32) {
        #pragma unroll
        for (int i = 0; i < 8; i++) {
            int v = tid + i * 256;
            int d = v >> 5, tl = v & 31;
            ks[tl][d] = kbase[(long)d * T + t0 + tl];
            vs[tl][d] = vbase[(long)d * T + t0 + tl];
        }
        __syncthreads();
        #pragma unroll
        for (int tl = 0; tl < 32; tl++) {
            float a[4], bb[4];
            #pragma unroll
            for (int i = 0; i < 4; i++) a[i]  = ks[tl][ty * 4 + i];
            #pragma unroll
            for (int j = 0; j < 4; j++) bb[j] = vs[tl][tx * 4 + j];
            #pragma unroll
            for (int i = 0; i < 4; i++)
                #pragma unroll
                for (int j = 0; j < 4; j++)
                    acc[i][j] = fmaf(a[i], bb[j], acc[i][j]);
        }
        __syncthreads();
    }
    float* p = part + ((long)bh * 8 + s) * (DH * DH);
    #pragma unroll
    for (int i = 0; i < 4; i++)
        #pragma unroll
        for (int j = 0; j < 4; j++)
            p[(ty * 4 + i) * DH + tx * 4 + j] = acc[i][j];
}

__global__ __launch_bounds__(256)
void ctx_reduce(const float* __restrict__ part, float* __restrict__ ctx)
{
    int bh = blockIdx.x;
    long base = (long)bh * 8 * (DH * DH);
    for (int i = threadIdx.x; i < DH * DH; i += 256) {
        float s = 0.f;
        #pragma unroll
        for (int sp = 0; sp < 8; sp++) s += part[base + (long)sp * (DH * DH) + i];
        ctx[(long)bh * (DH * DH) + i] = s;
    }
}

// ----- Weff[b][o][h*64+d] = sum_e Wout[o][h*64+e] * ctx[b][h][d][e] ---------
// output tf32-rounded (consumed by GEMM2 as A)
__global__ __launch_bounds__(256)
void make_weff(const float* __restrict__ ctx, const float* __restrict__ Wout,
               float* __restrict__ weff)
{
    __shared__ float cs[DH][DH];   // ctx[d][e]
    int b = blockIdx.x, h = blockIdx.y;
    const float* c = ctx + (long)(b * H + h) * (DH * DH);
    for (int i = threadIdx.x; i < DH * DH; i += 256) cs[i >> 6][i & 63] = c[i];
    __syncthreads();

    #pragma unroll
    for (int oo = 0; oo < 2; oo++) {
        int o = threadIdx.x + oo * 256;
        float w[DH];
        #pragma unroll
        for (int e = 0; e < DH; e++) w[e] = Wout[(long)o * C + h * DH + e];
        for (int d = 0; d < DH; d++) {
            float s = 0.f;
            #pragma unroll
            for (int e = 0; e < DH; e++) s = fmaf(w[e], cs[d][e], s);
            weff[((long)b * C + o) * C + h * DH + d] = f2tf_f(s);
        }
    }
}

// --------------------- GroupNorm ------------------------------------------
__global__ __launch_bounds__(256)
void gn_stats(const float* __restrict__ y, float* __restrict__ stats)
{
    __shared__ float sm[32];
    int b = blockIdx.y, ch = blockIdx.x;
    const float* p = y + (long)b * C * T + (long)ch * 16384;
    float s = 0.f, ss = 0.f;
    for (int i = threadIdx.x * 4; i < 16384; i += 1024) {
        float4 v = *(const float4*)&p[i];
        s  += v.x + v.y + v.z + v.w;
        ss += v.x * v.x + v.y * v.y + v.z * v.z + v.w * v.w;
    }
    float S  = blockReduceSum(s, sm);
    float SS = blockReduceSum(ss, sm);
    if (threadIdx.x == 0) {
        stats[(b * 128 + ch) * 2 + 0] = S;
        stats[(b * 128 + ch) * 2 + 1] = SS;
    }
}

__global__ __launch_bounds__(128)
void gn_finalize(const float* __restrict__ stats, float* __restrict__ mr)
{
    __shared__ float sm[32];
    int b = blockIdx.x;
    float s  = stats[(b * 128 + threadIdx.x) * 2 + 0];
    float ss = stats[(b * 128 + threadIdx.x) * 2 + 1];
    float S  = blockReduceSum(s, sm);
    float SS = blockReduceSum(ss, sm);
    if (threadIdx.x == 0) {
        const float n = (float)((long)C * T);
        float mean = S / n;
        float var  = SS / n - mean * mean;
        mr[b * 2 + 0] = mean;
        mr[b * 2 + 1] = rsqrtf(var + GN_EPS);
    }
}

__global__ __launch_bounds__(256)
void gn_norm(const float* __restrict__ y, const float* __restrict__ mr,
             const float* __restrict__ gw, const float* __restrict__ gb,
             float* __restrict__ out)
{
    int b = blockIdx.y;
    long base = (long)b * C * T;
    int idx = (blockIdx.x * 256 + threadIdx.x) * 4;
    int c = idx >> 12;                 // / 4096
    float mean = mr[b * 2 + 0], rstd = mr[b * 2 + 1];
    float g   = gw[c] * rstd;
    float beta = gb[c] - mean * g;
    float4 v = *(const float4*)&y[base + idx];
    v.x = fmaf(v.x, g, beta);
    v.y = fmaf(v.y, g, beta);
    v.z = fmaf(v.z, g, beta);
    v.w = fmaf(v.w, g, beta);
    *(float4*)&out[base + idx] = v;
}

// ---------------------------------------------------------------------------
extern "C" void kernel_launch(void* const* d_in, const int* in_sizes, int n_in,
                              void* d_out, int out_size)
{
    const float* x     = (const float*)d_in[0];
    const float* Wqkv  = (const float*)d_in[1];
    const float* Wout  = (const float*)d_in[2];
    const float* bout  = (const float*)d_in[3];
    const float* gnw   = (const float*)d_in[4];
    const float* gnb   = (const float*)d_in[5];
    float* out = (float*)d_out;

    float *qkv, *y, *part, *ctx, *weff, *stats, *mr;
    cudaGetSymbolAddress((void**)&qkv,   g_qkv);
    cudaGetSymbolAddress((void**)&y,     g_y);
    cudaGetSymbolAddress((void**)&part,  g_ctx_part);
    cudaGetSymbolAddress((void**)&ctx,   g_ctx);
    cudaGetSymbolAddress((void**)&weff,  g_weff);
    cudaGetSymbolAddress((void**)&stats, g_stats);
    cudaGetSymbolAddress((void**)&mr,    g_mr);

    float* xr = y;        // reuse g_y as rounded-x scratch (free until GEMM2)
    float* wqkvr = weff;  // reuse g_weff as rounded-Wqkv scratch (free until make_weff)

    cudaFuncSetAttribute(tgemm_tf32,
                         cudaFuncAttributeMaxDynamicSharedMemorySize, TGEMM_SMEM);

    // 0) pre-round inputs to tf32 (rna) so GEMMs skip inner-loop CVT
    round_tf32<<<(B * C * T / 4 + 255) / 256, 256>>>(x, xr, B * C * T / 4);
    round_tf32<<<(QKV_CH * C / 4 + 255) / 256, 256>>>(Wqkv, wqkvr, QKV_CH * C / 4);

    // 1) qkv = Wqkv @ x            [1536x512] @ [512x4096] per batch
    tgemm_tf32<<<dim3(T / BN, QKV_CH / BM, B), 256, TGEMM_SMEM>>>(
        wqkvr, 0L, xr, (long)C * T, qkv, (long)QKV_CH * T,
        QKV_CH, T, C, nullptr);

    // 2) softmaxes (softmax_q writes tf32-rounded q for GEMM2)
    softmax_q<<<dim3(T / 256, H, B), 256>>>(qkv);
    softmax_k<<<B * HID, 256>>>(qkv);

    // 3) context = k @ v^T  (split-K 8) then reduce
    ctx_partial<<<dim3(8, B * H), 256>>>(qkv, part);
    ctx_reduce<<<B * H, 256>>>(part, ctx);

    // 4) fold Wout with context (writes tf32-rounded weff)
    make_weff<<<dim3(B, H), 256>>>(ctx, Wout, weff);

    // 5) y = Weff @ q + b_out      [512x512] @ [512x4096] per batch
    tgemm_tf32<<<dim3(T / BN, C / BM, B), 256, TGEMM_SMEM>>>(
        weff, (long)C * C, qkv, (long)QKV_CH * T, y, (long)C * T,
        C, T, C, bout);

    // 6) GroupNorm
    gn_stats<<<dim3(128, B), 256>>>(y, stats);
    gn_finalize<<<B, 128>>>(stats, mr);
    gn_norm<<<dim3((C * T) / 1024, B), 256>>>(y, mr, gnw, gnb, out);
}

// round 7
// speedup vs baseline: 3.5314x; 1.3572x over previous
#include <cuda_runtime.h>
#include <cuda_fp16.h>
#include <cstdint>

// ---------------------------------------------------------------------------
// LinearAttention: qkv = Wqkv@x ; q=softmax_d(q)*scale ; k=softmax_t(k)
// ctx = k@v^T (64x64 per b,h) ; Weff = Wout*ctx fold ; y = Weff@q + b_out
// GroupNorm(1) over (c,t) per batch.
// b=16, c=512, t=4096, heads=8, dh=64, hidden=512
// GEMMs: fp16 mma.sync m16n8k16 (fp32 accum), ldmatrix frags, 4-stage cp.async.
// fp16 has the same 11-bit significand as tf32 -> same accuracy class.
// ---------------------------------------------------------------------------

#define B   16
#define C   512
#define T   4096
#define H   8
#define DH  64
#define HID 512
#define QKV_CH 1536
#define SCALE 0.125f   // 64^-0.5
#define GN_EPS 1e-5f

// Scratch (static device arrays: allocation-free rule)
__device__ float  g_qkv[(size_t)B * QKV_CH * T];          // 402 MB fp32
__device__ float  g_y[(size_t)B * C * T];                 // 134 MB
__device__ __half g_xh[(size_t)B * C * T];                // 67 MB
__device__ __half g_qh[(size_t)B * HID * T];              // 64 MB
__device__ __half g_wqkvh[(size_t)QKV_CH * C];            // 1.5 MB
__device__ __half g_weffh[(size_t)B * C * C];             // 8 MB
__device__ float  g_ctx_part[(size_t)B * H * 8 * DH * DH];// 16 MB
__device__ float  g_ctx[(size_t)B * H * DH * DH];         // 2 MB
__device__ float  g_stats[B * 128 * 2];
__device__ float  g_mr[B * 2];

// ========================= helpers =========================================
__device__ __forceinline__ uint32_t smem_u32(const void* p) {
    uint32_t a;
    asm("{ .reg .u64 t; cvta.to.shared.u64 t, %1; cvt.u32.u64 %0, t; }"
        : "=r"(a) : "l"(p));
    return a;
}

__device__ __forceinline__ void cp_async16(uint32_t smem_dst, const void* gsrc) {
    asm volatile("cp.async.cg.shared.global [%0], [%1], 16;"
                 :: "r"(smem_dst), "l"(gsrc));
}
__device__ __forceinline__ void cp_commit() {
    asm volatile("cp.async.commit_group;" ::: "memory");
}
template <int N>
__device__ __forceinline__ void cp_wait() {
    asm volatile("cp.async.wait_group %0;" :: "n"(N) : "memory");
}

__device__ __forceinline__ void ldsm_x4(uint32_t* r, uint32_t addr) {
    asm volatile("ldmatrix.sync.aligned.m8n8.x4.shared.b16 {%0,%1,%2,%3}, [%4];"
                 : "=r"(r[0]), "=r"(r[1]), "=r"(r[2]), "=r"(r[3]) : "r"(addr));
}
__device__ __forceinline__ void ldsm_x4_trans(uint32_t* r, uint32_t addr) {
    asm volatile("ldmatrix.sync.aligned.m8n8.x4.trans.shared.b16 {%0,%1,%2,%3}, [%4];"
                 : "=r"(r[0]), "=r"(r[1]), "=r"(r[2]), "=r"(r[3]) : "r"(addr));
}

__device__ __forceinline__ void mma16n8k16(float* c, const uint32_t* a,
                                           const uint32_t* b) {
    asm volatile(
        "mma.sync.aligned.m16n8k16.row.col.f32.f16.f16.f32 "
        "{%0,%1,%2,%3}, {%4,%5,%6,%7}, {%8,%9}, {%0,%1,%2,%3};"
        : "+f"(c[0]), "+f"(c[1]), "+f"(c[2]), "+f"(c[3])
        : "r"(a[0]), "r"(a[1]), "r"(a[2]), "r"(a[3]),
          "r"(b[0]), "r"(b[1]));
}

// ========================= fp16 HMMA GEMM ==================================
// Y[b][M,N](f32) = A[b][M,K](f16) @ X[b][K,N](f16) (+bias[m])
// Tile 128x256x32, 8 warps (2m x 4n) of 64x64, 4-stage cp.async, ldmatrix.
#define BM 128
#define BN 256
#define BK 32
#define ASH 40     // halves per A row (pad 8): LDSM rows stride 80B, conflict-free
#define BSH 264    // halves per B row (pad 8): LDSM rows stride 528B, conflict-free
#define A_BYTES (BM * ASH * 2)            // 10240
#define B_BYTES (BK * BSH * 2)            // 16896
#define STAGE_BYTES (A_BYTES + B_BYTES)   // 27136
#define NSTAGE 4
#define TGEMM_SMEM (NSTAGE * STAGE_BYTES) // 108544

__global__ __launch_bounds__(256, 1)
void hgemm(const __half* __restrict__ A, long strideA,
           const __half* __restrict__ X, long strideX,
           float* __restrict__ Y, long strideY,
           int M, int N, int K, const float* __restrict__ bias)
{
    extern __shared__ char dsm[];
    const int tid = threadIdx.x;
    const int wid = tid >> 5;
    const int lane = tid & 31;
    const int gid = lane >> 2;      // mma group row (0..7)
    const int tg  = lane & 3;       // thread in group
    const int lg  = lane >> 3;      // ldsm tile id (0..3)
    const int lr  = lane & 7;       // ldsm row in tile
    const int b  = blockIdx.z;
    const int bm = blockIdx.y * BM, bn = blockIdx.x * BN;
    const __half* Ab = A + (long)b * strideA + (long)bm * K;
    const __half* Xb = X + (long)b * strideX + bn;

    const uint32_t smem0 = smem_u32(dsm);
    const int warpM = (wid >> 2) * 64;
    const int warpN = (wid & 3) * 64;

    // per-thread ldsm base offsets (bytes) within a stage
    // A tile for (mt,kk): rows warpM+mt*16+(lg&1)*8+lr, col halves kk*16+(lg>>1)*8
    const uint32_t a_ldsm = (uint32_t)(((warpM + (lg & 1) * 8 + lr) * ASH
                                        + (lg >> 1) * 8) * 2);
    // B tile for (kk,p): rows kk*16+(lg&1)*8+lr, col halves warpN+p*16+(lg>>1)*8
    const uint32_t b_ldsm = (uint32_t)A_BYTES
        + (uint32_t)((((lg & 1) * 8 + lr) * BSH + warpN + (lg >> 1) * 8) * 2);

    float acc[4][8][4];
    #pragma unroll
    for (int mt = 0; mt < 4; mt++)
        #pragma unroll
        for (int nt = 0; nt < 8; nt++)
            #pragma unroll
            for (int r = 0; r < 4; r++) acc[mt][nt][r] = 0.f;

    const int niter = K / BK;   // 16

    auto load_stage = [&](int it) {
        const int k0 = it * BK;
        const uint32_t sb = smem0 + (it % NSTAGE) * STAGE_BYTES;
        #pragma unroll
        for (int i = 0; i < 2; i++) {          // A: 512 chunks of 8 halves
            int v = tid + i * 256;
            int row = v >> 2, c8 = (v & 3) * 8;
            cp_async16(sb + (uint32_t)((row * ASH + c8) * 2),
                       &Ab[(long)row * K + k0 + c8]);
        }
        #pragma unroll
        for (int i = 0; i < 4; i++) {          // B: 1024 chunks
            int v = tid + i * 256;
            int kr = v >> 5, c8 = (v & 31) * 8;
            cp_async16(sb + (uint32_t)A_BYTES + (uint32_t)((kr * BSH + c8) * 2),
                       &Xb[(long)(k0 + kr) * N + c8]);
        }
        cp_commit();
    };

    load_stage(0);
    load_stage(1);
    load_stage(2);

    for (int it = 0; it < niter; it++) {
        if (it + 3 < niter) { load_stage(it + 3); cp_wait<3>(); }
        else {
            int rem = niter - 1 - it;
            if (rem >= 3) cp_wait<3>();
            else if (rem == 2) cp_wait<2>();
            else if (rem == 1) cp_wait<1>();
            else cp_wait<0>();
        }
        __syncthreads();

        const uint32_t sb = smem0 + (it % NSTAGE) * STAGE_BYTES;

        #pragma unroll
        for (int kk = 0; kk < 2; kk++) {
            uint32_t afr[4][4], bfr[8][2];
            #pragma unroll
            for (int mt = 0; mt < 4; mt++)
                ldsm_x4(afr[mt], sb + a_ldsm
                        + (uint32_t)((mt * 16 * ASH + kk * 16) * 2));
            #pragma unroll
            for (int p = 0; p < 4; p++) {
                uint32_t r4[4];
                ldsm_x4_trans(r4, sb + b_ldsm
                              + (uint32_t)((kk * 16 * BSH + p * 16) * 2));
                bfr[2 * p][0] = r4[0]; bfr[2 * p][1] = r4[1];
                bfr[2 * p + 1][0] = r4[2]; bfr[2 * p + 1][1] = r4[3];
            }
            #pragma unroll
            for (int mt = 0; mt < 4; mt++)
                #pragma unroll
                for (int nt = 0; nt < 8; nt++)
                    mma16n8k16(acc[mt][nt], afr[mt], bfr[nt]);
        }
        __syncthreads();
    }

    // epilogue: c0:(gid, 2tg) c1:(gid, 2tg+1) c2:(gid+8, 2tg) c3:(gid+8, 2tg+1)
    float* Yb = Y + (long)b * strideY;
    #pragma unroll
    for (int mt = 0; mt < 4; mt++) {
        int row0 = bm + warpM + mt * 16 + gid;
        float bv0 = bias ? bias[row0] : 0.f;
        float bv1 = bias ? bias[row0 + 8] : 0.f;
        #pragma unroll
        for (int nt = 0; nt < 8; nt++) {
            int col = bn + warpN + nt * 8 + tg * 2;
            float2 o0, o1;
            o0.x = acc[mt][nt][0] + bv0; o0.y = acc[mt][nt][1] + bv0;
            o1.x = acc[mt][nt][2] + bv1; o1.y = acc[mt][nt][3] + bv1;
            *(float2*)&Yb[(long)row0 * N + col] = o0;
            *(float2*)&Yb[(long)(row0 + 8) * N + col] = o1;
        }
    }
}

// --------------------- fp32 -> fp16 convert pass ----------------------------
__global__ __launch_bounds__(256)
void conv_half(const float* __restrict__ in, __half* __restrict__ out, int n4)
{
    int i = blockIdx.x * 256 + threadIdx.x;
    if (i >= n4) return;
    float4 v = ((const float4*)in)[i];
    __half2 h0 = __floats2half2_rn(v.x, v.y);
    __half2 h1 = __floats2half2_rn(v.z, v.w);
    ((__half2*)out)[2 * i] = h0;
    ((__half2*)out)[2 * i + 1] = h1;
}

// ------------------------- block reduce helpers ----------------------------
__device__ __forceinline__ float blockReduceSum(float v, float* sm) {
    __syncthreads();
    #pragma unroll
    for (int o = 16; o; o >>= 1) v += __shfl_down_sync(0xffffffffu, v, o);
    int lane = threadIdx.x & 31, w = threadIdx.x >> 5;
    if (lane == 0) sm[w] = v;
    __syncthreads();
    if (w == 0) {
        v = (lane < (int)(blockDim.x >> 5)) ? sm[lane] : 0.f;
        #pragma unroll
        for (int o = 16; o; o >>= 1) v += __shfl_down_sync(0xffffffffu, v, o);
        if (lane == 0) sm[0] = v;
    }
    __syncthreads();
    return sm[0];
}

__device__ __forceinline__ float blockReduceMax(float v, float* sm) {
    __syncthreads();
    #pragma unroll
    for (int o = 16; o; o >>= 1) v = fmaxf(v, __shfl_down_sync(0xffffffffu, v, o));
    int lane = threadIdx.x & 31, w = threadIdx.x >> 5;
    if (lane == 0) sm[w] = v;
    __syncthreads();
    if (w == 0) {
        v = (lane < (int)(blockDim.x >> 5)) ? sm[lane] : -1e30f;
        #pragma unroll
        for (int o = 16; o; o >>= 1) v = fmaxf(v, __shfl_down_sync(0xffffffffu, v, o));
        if (lane == 0) sm[0] = v;
    }
    __syncthreads();
    return sm[0];
}

// --------------------- softmax over feature dim (q), *SCALE -> half qh ------
__global__ __launch_bounds__(256)
void softmax_q(const float* __restrict__ qkv, __half* __restrict__ qh)
{
    int t = blockIdx.x * 256 + threadIdx.x;
    int h = blockIdx.y, b = blockIdx.z;
    const float* base = qkv + (long)b * QKV_CH * T + (long)h * DH * T + t;
    __half* obase = qh + (long)b * HID * T + (long)h * DH * T + t;

    float v[DH];
    float mx = -1e30f;
    #pragma unroll
    for (int d = 0; d < DH; d++) { v[d] = base[(long)d * T]; mx = fmaxf(mx, v[d]); }
    float s = 0.f;
    #pragma unroll
    for (int d = 0; d < DH; d++) { v[d] = __expf(v[d] - mx); s += v[d]; }
    float inv = SCALE / s;
    #pragma unroll
    for (int d = 0; d < DH; d++) obase[(long)d * T] = __float2half(v[d] * inv);
}

// --------------------- softmax over time dim (k), fp32 in-place -------------
__global__ __launch_bounds__(256)
void softmax_k(float* __restrict__ qkv)
{
    __shared__ float sm[32];
    int r = blockIdx.x;              // b*512 + c
    int b = r >> 9, c = r & 511;
    float* row = qkv + (long)b * QKV_CH * T + (long)(HID + c) * T;
    int tid = threadIdx.x;

    float v[16];
    float mx = -1e30f;
    #pragma unroll
    for (int i = 0; i < 16; i++) { v[i] = row[tid + i * 256]; mx = fmaxf(mx, v[i]); }
    mx = blockReduceMax(mx, sm);
    float s = 0.f;
    #pragma unroll
    for (int i = 0; i < 16; i++) { v[i] = __expf(v[i] - mx); s += v[i]; }
    s = blockReduceSum(s, sm);
    float inv = 1.f / s;
    #pragma unroll
    for (int i = 0; i < 16; i++) row[tid + i * 256] = v[i] * inv;
}

// --------------------- context partial: k @ v^T (split-K over t) ------------
__global__ __launch_bounds__(256)
void ctx_partial(const float* __restrict__ qkv, float* __restrict__ part)
{
    __shared__ float ks[32][65];
    __shared__ float vs[32][65];
    int s = blockIdx.x, bh = blockIdx.y;
    int b = bh >> 3, h = bh & 7;
    const float* kbase = qkv + (long)b * QKV_CH * T + (long)(HID + h * DH) * T;
    const float* vbase = qkv + (long)b * QKV_CH * T + (long)(2 * HID + h * DH) * T;
    int tid = threadIdx.x, tx = tid & 15, ty = tid >> 4;

    float acc[4][4] = {};
    for (int t0 = s * 512; t0 < s * 512 + 512; t0 += 32) {
        #pragma unroll
        for (int i = 0; i < 8; i++) {
            int v = tid + i * 256;
            int d = v >> 5, tl = v & 31;
            ks[tl][d] = kbase[(long)d * T + t0 + tl];
            vs[tl][d] = vbase[(long)d * T + t0 + tl];
        }
        __syncthreads();
        #pragma unroll
        for (int tl = 0; tl < 32; tl++) {
            float a[4], bb[4];
            #pragma unroll
            for (int i = 0; i < 4; i++) a[i]  = ks[tl][ty * 4 + i];
            #pragma unroll
            for (int j = 0; j < 4; j++) bb[j] = vs[tl][tx * 4 + j];
            #pragma unroll
            for (int i = 0; i < 4; i++)
                #pragma unroll
                for (int j = 0; j < 4; j++)
                    acc[i][j] = fmaf(a[i], bb[j], acc[i][j]);
        }
        __syncthreads();
    }
    float* p = part + ((long)bh * 8 + s) * (DH * DH);
    #pragma unroll
    for (int i = 0; i < 4; i++)
        #pragma unroll
        for (int j = 0; j < 4; j++)
            p[(ty * 4 + i) * DH + tx * 4 + j] = acc[i][j];
}

__global__ __launch_bounds__(256)
void ctx_reduce(const float* __restrict__ part, float* __restrict__ ctx)
{
    int bh = blockIdx.x;
    long base = (long)bh * 8 * (DH * DH);
    for (int i = threadIdx.x; i < DH * DH; i += 256) {
        float s = 0.f;
        #pragma unroll
        for (int sp = 0; sp < 8; sp++) s += part[base + (long)sp * (DH * DH) + i];
        ctx[(long)bh * (DH * DH) + i] = s;
    }
}

// ----- Weff[b][o][h*64+d] = sum_e Wout[o][h*64+e] * ctx[b][h][d][e] -> half --
__global__ __launch_bounds__(256)
void make_weff(const float* __restrict__ ctx, const float* __restrict__ Wout,
               __half* __restrict__ weffh)
{
    __shared__ float cs[DH][DH];   // ctx[d][e]
    int b = blockIdx.x, h = blockIdx.y;
    const float* c = ctx + (long)(b * H + h) * (DH * DH);
    for (int i = threadIdx.x; i < DH * DH; i += 256) cs[i >> 6][i & 63] = c[i];
    __syncthreads();

    #pragma unroll
    for (int oo = 0; oo < 2; oo++) {
        int o = threadIdx.x + oo * 256;
        float w[DH];
        #pragma unroll
        for (int e = 0; e < DH; e++) w[e] = Wout[(long)o * C + h * DH + e];
        for (int d = 0; d < DH; d++) {
            float s = 0.f;
            #pragma unroll
            for (int e = 0; e < DH; e++) s = fmaf(w[e], cs[d][e], s);
            weffh[((long)b * C + o) * C + h * DH + d] = __float2half(s);
        }
    }
}

// --------------------- GroupNorm ------------------------------------------
__global__ __launch_bounds__(256)
void gn_stats(const float* __restrict__ y, float* __restrict__ stats)
{
    __shared__ float sm[32];
    int b = blockIdx.y, ch = blockIdx.x;
    const float* p = y + (long)b * C * T + (long)ch * 16384;
    float s = 0.f, ss = 0.f;
    for (int i = threadIdx.x * 4; i < 16384; i += 1024) {
        float4 v = *(const float4*)&p[i];
        s  += v.x + v.y + v.z + v.w;
        ss += v.x * v.x + v.y * v.y + v.z * v.z + v.w * v.w;
    }
    float S  = blockReduceSum(s, sm);
    float SS = blockReduceSum(ss, sm);
    if (threadIdx.x == 0) {
        stats[(b * 128 + ch) * 2 + 0] = S;
        stats[(b * 128 + ch) * 2 + 1] = SS;
    }
}

__global__ __launch_bounds__(128)
void gn_finalize(const float* __restrict__ stats, float* __restrict__ mr)
{
    __shared__ float sm[32];
    int b = blockIdx.x;
    float s  = stats[(b * 128 + threadIdx.x) * 2 + 0];
    float ss = stats[(b * 128 + threadIdx.x) * 2 + 1];
    float S  = blockReduceSum(s, sm);
    float SS = blockReduceSum(ss, sm);
    if (threadIdx.x == 0) {
        const float n = (float)((long)C * T);
        float mean = S / n;
        float var  = SS / n - mean * mean;
        mr[b * 2 + 0] = mean;
        mr[b * 2 + 1] = rsqrtf(var + GN_EPS);
    }
}

__global__ __launch_bounds__(256)
void gn_norm(const float* __restrict__ y, const float* __restrict__ mr,
             const float* __restrict__ gw, const float* __restrict__ gb,
             float* __restrict__ out)
{
    int b = blockIdx.y;
    long base = (long)b * C * T;
    int idx = (blockIdx.x * 256 + threadIdx.x) * 4;
    int c = idx >> 12;                 // / 4096
    float mean = mr[b * 2 + 0], rstd = mr[b * 2 + 1];
    float g   = gw[c] * rstd;
    float beta = gb[c] - mean * g;
    float4 v = *(const float4*)&y[base + idx];
    v.x = fmaf(v.x, g, beta);
    v.y = fmaf(v.y, g, beta);
    v.z = fmaf(v.z, g, beta);
    v.w = fmaf(v.w, g, beta);
    *(float4*)&out[base + idx] = v;
}

// ---------------------------------------------------------------------------
extern "C" void kernel_launch(void* const* d_in, const int* in_sizes, int n_in,
                              void* d_out, int out_size)
{
    const float* x     = (const float*)d_in[0];
    const float* Wqkv  = (const float*)d_in[1];
    const float* Wout  = (const float*)d_in[2];
    const float* bout  = (const float*)d_in[3];
    const float* gnw   = (const float*)d_in[4];
    const float* gnb   = (const float*)d_in[5];
    float* out = (float*)d_out;

    float *qkv, *y, *part, *ctx, *stats, *mr;
    __half *xh, *qh, *wqkvh, *weffh;
    cudaGetSymbolAddress((void**)&qkv,   g_qkv);
    cudaGetSymbolAddress((void**)&y,     g_y);
    cudaGetSymbolAddress((void**)&part,  g_ctx_part);
    cudaGetSymbolAddress((void**)&ctx,   g_ctx);
    cudaGetSymbolAddress((void**)&stats, g_stats);
    cudaGetSymbolAddress((void**)&mr,    g_mr);
    cudaGetSymbolAddress((void**)&xh,    g_xh);
    cudaGetSymbolAddress((void**)&qh,    g_qh);
    cudaGetSymbolAddress((void**)&wqkvh, g_wqkvh);
    cudaGetSymbolAddress((void**)&weffh, g_weffh);

    cudaFuncSetAttribute(hgemm,
                         cudaFuncAttributeMaxDynamicSharedMemorySize, TGEMM_SMEM);

    // 0) convert inputs to fp16
    conv_half<<<(B * C * T / 4 + 255) / 256, 256>>>(x, xh, B * C * T / 4);
    conv_half<<<(QKV_CH * C / 4 + 255) / 256, 256>>>(Wqkv, wqkvh, QKV_CH * C / 4);

    // 1) qkv = Wqkv @ x            [1536x512] @ [512x4096] per batch
    hgemm<<<dim3(T / BN, QKV_CH / BM, B), 256, TGEMM_SMEM>>>(
        wqkvh, 0L, xh, (long)C * T, qkv, (long)QKV_CH * T,
        QKV_CH, T, C, nullptr);

    // 2) softmaxes (q -> half buffer; k in-place fp32)
    softmax_q<<<dim3(T / 256, H, B), 256>>>(qkv, qh);
    softmax_k<<<B * HID, 256>>>(qkv);

    // 3) context = k @ v^T  (split-K 8) then reduce
    ctx_partial<<<dim3(8, B * H), 256>>>(qkv, part);
    ctx_reduce<<<B * H, 256>>>(part, ctx);

    // 4) fold Wout with context -> half
    make_weff<<<dim3(B, H), 256>>>(ctx, Wout, weffh);

    // 5) y = Weff @ q + b_out      [512x512] @ [512x4096] per batch
    hgemm<<<dim3(T / BN, C / BM, B), 256, TGEMM_SMEM>>>(
        weffh, (long)C * C, qh, (long)HID * T, y, (long)C * T,
        C, T, C, bout);

    // 6) GroupNorm
    gn_stats<<<dim3(128, B), 256>>>(y, stats);
    gn_finalize<<<B, 128>>>(stats, mr);
    gn_norm<<<dim3((C * T) / 1024, B), 256>>>(y, mr, gnw, gnb, out);
}

// round 8
// speedup vs baseline: 3.7937x; 1.0743x over previous
#include <cuda_runtime.h>
#include <cuda_fp16.h>
#include <cstdint>

// ---------------------------------------------------------------------------
// LinearAttention fused pipeline (fp16 HMMA GEMMs, fused softmax_q + GN stats)
// b=16, c=512, t=4096, heads=8, dh=64, hidden=512
// ---------------------------------------------------------------------------

#define B   16
#define C   512
#define T   4096
#define H   8
#define DH  64
#define HID 512
#define QKV_CH 1536
#define SCALE 0.125f   // 64^-0.5
#define GN_EPS 1e-5f

// Scratch (static device arrays: allocation-free rule)
__device__ float  g_y[(size_t)B * C * T];                 // 134 MB
__device__ __half g_xh[(size_t)B * C * T];                // 67 MB
__device__ __half g_qh[(size_t)B * HID * T];              // 67 MB (softmaxed q)
__device__ __half g_kh[(size_t)B * HID * T];              // 67 MB (k logits->softmax)
__device__ __half g_vh[(size_t)B * HID * T];              // 67 MB
__device__ __half g_wqkvh[(size_t)QKV_CH * C];            // 1.5 MB
__device__ __half g_weffh[(size_t)B * C * C];             // 8 MB
__device__ float  g_ctx_part[(size_t)B * H * 8 * DH * DH];// 16 MB
__device__ float  g_ctx[(size_t)B * H * DH * DH];         // 2 MB
__device__ float  g_stats[B * 64 * 2];
__device__ float  g_mr[B * 2];

// ========================= helpers =========================================
__device__ __forceinline__ uint32_t smem_u32(const void* p) {
    uint32_t a;
    asm("{ .reg .u64 t; cvta.to.shared.u64 t, %1; cvt.u32.u64 %0, t; }"
        : "=r"(a) : "l"(p));
    return a;
}

__device__ __forceinline__ void cp_async16(uint32_t smem_dst, const void* gsrc) {
    asm volatile("cp.async.cg.shared.global [%0], [%1], 16;"
                 :: "r"(smem_dst), "l"(gsrc));
}
__device__ __forceinline__ void cp_commit() {
    asm volatile("cp.async.commit_group;" ::: "memory");
}
template <int N>
__device__ __forceinline__ void cp_wait() {
    asm volatile("cp.async.wait_group %0;" :: "n"(N) : "memory");
}

__device__ __forceinline__ void ldsm_x4(uint32_t* r, uint32_t addr) {
    asm volatile("ldmatrix.sync.aligned.m8n8.x4.shared.b16 {%0,%1,%2,%3}, [%4];"
                 : "=r"(r[0]), "=r"(r[1]), "=r"(r[2]), "=r"(r[3]) : "r"(addr));
}
__device__ __forceinline__ void ldsm_x4_trans(uint32_t* r, uint32_t addr) {
    asm volatile("ldmatrix.sync.aligned.m8n8.x4.trans.shared.b16 {%0,%1,%2,%3}, [%4];"
                 : "=r"(r[0]), "=r"(r[1]), "=r"(r[2]), "=r"(r[3]) : "r"(addr));
}

__device__ __forceinline__ void mma16n8k16(float* c, const uint32_t* a,
                                           const uint32_t* b) {
    asm volatile(
        "mma.sync.aligned.m16n8k16.row.col.f32.f16.f16.f32 "
        "{%0,%1,%2,%3}, {%4,%5,%6,%7}, {%8,%9}, {%0,%1,%2,%3};"
        : "+f"(c[0]), "+f"(c[1]), "+f"(c[2]), "+f"(c[3])
        : "r"(a[0]), "r"(a[1]), "r"(a[2]), "r"(a[3]),
          "r"(b[0]), "r"(b[1]));
}

// ------------------------- block reduce helper -----------------------------
__device__ __forceinline__ float blockReduceSum(float v, float* sm) {
    __syncthreads();
    #pragma unroll
    for (int o = 16; o; o >>= 1) v += __shfl_down_sync(0xffffffffu, v, o);
    int lane = threadIdx.x & 31, w = threadIdx.x >> 5;
    if (lane == 0) sm[w] = v;
    __syncthreads();
    if (w == 0) {
        v = (lane < (int)(blockDim.x >> 5)) ? sm[lane] : 0.f;
        #pragma unroll
        for (int o = 16; o; o >>= 1) v += __shfl_down_sync(0xffffffffu, v, o);
        if (lane == 0) sm[0] = v;
    }
    __syncthreads();
    return sm[0];
}

__device__ __forceinline__ float blockReduceMax(float v, float* sm) {
    __syncthreads();
    #pragma unroll
    for (int o = 16; o; o >>= 1) v = fmaxf(v, __shfl_down_sync(0xffffffffu, v, o));
    int lane = threadIdx.x & 31, w = threadIdx.x >> 5;
    if (lane == 0) sm[w] = v;
    __syncthreads();
    if (w == 0) {
        v = (lane < (int)(blockDim.x >> 5)) ? sm[lane] : -1e30f;
        #pragma unroll
        for (int o = 16; o; o >>= 1) v = fmaxf(v, __shfl_down_sync(0xffffffffu, v, o));
        if (lane == 0) sm[0] = v;
    }
    __syncthreads();
    return sm[0];
}

// ========================= fp16 HMMA GEMM ==================================
// Tile 128x256x32, 8 warps (2m x 4n) of 64x64, 4-stage cp.async, ldmatrix.
// MODE 1 (GEMM1): epilogue splits q/k/v; q gets feature-softmax*SCALE -> qh,
//                 k/v converted to fp16 -> kh/vh. No fp32 output.
// MODE 2 (GEMM2): fp32 output + bias, per-block GN partial sums -> stats.
#define BM 128
#define BN 256
#define BK 32
#define ASH 40
#define BSH 264
#define A_BYTES (BM * ASH * 2)
#define B_BYTES (BK * BSH * 2)
#define STAGE_BYTES (A_BYTES + B_BYTES)   // 27136
#define NSTAGE 4
#define TGEMM_SMEM (NSTAGE * STAGE_BYTES) // 108544

template <int MODE>
__global__ __launch_bounds__(256, 1)
void hgemm(const __half* __restrict__ A, long strideA,
           const __half* __restrict__ X, long strideX,
           float* __restrict__ Y, long strideY,
           int M, int N, int K, const float* __restrict__ bias,
           __half* __restrict__ q_out, __half* __restrict__ k_out,
           __half* __restrict__ v_out, float* __restrict__ stats)
{
    extern __shared__ char dsm[];
    __shared__ float redsm[32];
    const int tid = threadIdx.x;
    const int wid = tid >> 5;
    const int lane = tid & 31;
    const int gid = lane >> 2;
    const int tg  = lane & 3;
    const int lg  = lane >> 3;
    const int lr  = lane & 7;
    const int b  = blockIdx.z;
    const int bm = blockIdx.y * BM, bn = blockIdx.x * BN;
    const __half* Ab = A + (long)b * strideA + (long)bm * K;
    const __half* Xb = X + (long)b * strideX + bn;

    const uint32_t smem0 = smem_u32(dsm);
    const int warpM = (wid >> 2) * 64;
    const int warpN = (wid & 3) * 64;

    const uint32_t a_ldsm = (uint32_t)(((warpM + (lg & 1) * 8 + lr) * ASH
                                        + (lg >> 1) * 8) * 2);
    const uint32_t b_ldsm = (uint32_t)A_BYTES
        + (uint32_t)((((lg & 1) * 8 + lr) * BSH + warpN + (lg >> 1) * 8) * 2);

    float acc[4][8][4];
    #pragma unroll
    for (int mt = 0; mt < 4; mt++)
        #pragma unroll
        for (int nt = 0; nt < 8; nt++)
            #pragma unroll
            for (int r = 0; r < 4; r++) acc[mt][nt][r] = 0.f;

    const int niter = K / BK;   // 16

    auto load_stage = [&](int it) {
        const int k0 = it * BK;
        const uint32_t sb = smem0 + (it % NSTAGE) * STAGE_BYTES;
        #pragma unroll
        for (int i = 0; i < 2; i++) {
            int v = tid + i * 256;
            int row = v >> 2, c8 = (v & 3) * 8;
            cp_async16(sb + (uint32_t)((row * ASH + c8) * 2),
                       &Ab[(long)row * K + k0 + c8]);
        }
        #pragma unroll
        for (int i = 0; i < 4; i++) {
            int v = tid + i * 256;
            int kr = v >> 5, c8 = (v & 31) * 8;
            cp_async16(sb + (uint32_t)A_BYTES + (uint32_t)((kr * BSH + c8) * 2),
                       &Xb[(long)(k0 + kr) * N + c8]);
        }
        cp_commit();
    };

    load_stage(0);
    load_stage(1);
    load_stage(2);

    for (int it = 0; it < niter; it++) {
        if (it + 3 < niter) { load_stage(it + 3); cp_wait<3>(); }
        else {
            int rem = niter - 1 - it;
            if (rem >= 3) cp_wait<3>();
            else if (rem == 2) cp_wait<2>();
            else if (rem == 1) cp_wait<1>();
            else cp_wait<0>();
        }
        __syncthreads();

        const uint32_t sb = smem0 + (it % NSTAGE) * STAGE_BYTES;

        #pragma unroll
        for (int kk = 0; kk < 2; kk++) {
            uint32_t afr[4][4], bfr[8][2];
            #pragma unroll
            for (int mt = 0; mt < 4; mt++)
                ldsm_x4(afr[mt], sb + a_ldsm
                        + (uint32_t)((mt * 16 * ASH + kk * 16) * 2));
            #pragma unroll
            for (int p = 0; p < 4; p++) {
                uint32_t r4[4];
                ldsm_x4_trans(r4, sb + b_ldsm
                              + (uint32_t)((kk * 16 * BSH + p * 16) * 2));
                bfr[2 * p][0] = r4[0]; bfr[2 * p][1] = r4[1];
                bfr[2 * p + 1][0] = r4[2]; bfr[2 * p + 1][1] = r4[3];
            }
            #pragma unroll
            for (int mt = 0; mt < 4; mt++)
                #pragma unroll
                for (int nt = 0; nt < 8; nt++)
                    mma16n8k16(acc[mt][nt], afr[mt], bfr[nt]);
        }
        __syncthreads();
    }

    if (MODE == 1) {
        // ---- GEMM1 epilogue: q softmax / k,v convert, all fp16 ----
        const int ch0 = bm + warpM;   // warp covers channels ch0..ch0+63
        if (ch0 < HID) {
            // feature softmax over the warp's 64 rows (one head), per column
            float mxA[8], mxB[8], scA[8], scB[8];
            #pragma unroll
            for (int nt = 0; nt < 8; nt++) {
                float a = -1e30f, bb = -1e30f;
                #pragma unroll
                for (int mt = 0; mt < 4; mt++) {
                    a  = fmaxf(a,  fmaxf(acc[mt][nt][0], acc[mt][nt][2]));
                    bb = fmaxf(bb, fmaxf(acc[mt][nt][1], acc[mt][nt][3]));
                }
                #pragma unroll
                for (int o = 4; o <= 16; o <<= 1) {
                    a  = fmaxf(a,  __shfl_xor_sync(0xffffffffu, a, o));
                    bb = fmaxf(bb, __shfl_xor_sync(0xffffffffu, bb, o));
                }
                mxA[nt] = a; mxB[nt] = bb;
            }
            #pragma unroll
            for (int nt = 0; nt < 8; nt++) {
                float sa = 0.f, sb2 = 0.f;
                #pragma unroll
                for (int mt = 0; mt < 4; mt++) {
                    acc[mt][nt][0] = __expf(acc[mt][nt][0] - mxA[nt]);
                    acc[mt][nt][2] = __expf(acc[mt][nt][2] - mxA[nt]);
                    sa += acc[mt][nt][0] + acc[mt][nt][2];
                    acc[mt][nt][1] = __expf(acc[mt][nt][1] - mxB[nt]);
                    acc[mt][nt][3] = __expf(acc[mt][nt][3] - mxB[nt]);
                    sb2 += acc[mt][nt][1] + acc[mt][nt][3];
                }
                #pragma unroll
                for (int o = 4; o <= 16; o <<= 1) {
                    sa  += __shfl_xor_sync(0xffffffffu, sa, o);
                    sb2 += __shfl_xor_sync(0xffffffffu, sb2, o);
                }
                scA[nt] = SCALE / sa; scB[nt] = SCALE / sb2;
            }
            __half* qb = q_out + (long)b * HID * T;
            #pragma unroll
            for (int mt = 0; mt < 4; mt++) {
                int ch = ch0 + mt * 16 + gid;
                #pragma unroll
                for (int nt = 0; nt < 8; nt++) {
                    int t = bn + warpN + nt * 8 + tg * 2;
                    *(__half2*)&qb[(long)ch * T + t] =
                        __floats2half2_rn(acc[mt][nt][0] * scA[nt],
                                          acc[mt][nt][1] * scB[nt]);
                    *(__half2*)&qb[(long)(ch + 8) * T + t] =
                        __floats2half2_rn(acc[mt][nt][2] * scA[nt],
                                          acc[mt][nt][3] * scB[nt]);
                }
            }
        } else {
            __half* dst = (ch0 < 2 * HID) ? k_out : v_out;
            const int chbase = ch0 - ((ch0 < 2 * HID) ? HID : 2 * HID);
            __half* db = dst + (long)b * HID * T;
            #pragma unroll
            for (int mt = 0; mt < 4; mt++) {
                int ch = chbase + mt * 16 + gid;
                #pragma unroll
                for (int nt = 0; nt < 8; nt++) {
                    int t = bn + warpN + nt * 8 + tg * 2;
                    *(__half2*)&db[(long)ch * T + t] =
                        __floats2half2_rn(acc[mt][nt][0], acc[mt][nt][1]);
                    *(__half2*)&db[(long)(ch + 8) * T + t] =
                        __floats2half2_rn(acc[mt][nt][2], acc[mt][nt][3]);
                }
            }
        }
    } else {
        // ---- GEMM2 epilogue: fp32 y + bias, GN partial sums ----
        float ls = 0.f, lss = 0.f;
        float* Yb = Y + (long)b * strideY;
        #pragma unroll
        for (int mt = 0; mt < 4; mt++) {
            int row0 = bm + warpM + mt * 16 + gid;
            float bv0 = bias[row0];
            float bv1 = bias[row0 + 8];
            #pragma unroll
            for (int nt = 0; nt < 8; nt++) {
                int col = bn + warpN + nt * 8 + tg * 2;
                float2 o0, o1;
                o0.x = acc[mt][nt][0] + bv0; o0.y = acc[mt][nt][1] + bv0;
                o1.x = acc[mt][nt][2] + bv1; o1.y = acc[mt][nt][3] + bv1;
                ls  += o0.x + o0.y + o1.x + o1.y;
                lss += o0.x * o0.x + o0.y * o0.y + o1.x * o1.x + o1.y * o1.y;
                *(float2*)&Yb[(long)row0 * N + col] = o0;
                *(float2*)&Yb[(long)(row0 + 8) * N + col] = o1;
            }
        }
        float S  = blockReduceSum(ls, redsm);
        float SS = blockReduceSum(lss, redsm);
        if (tid == 0) {
            int tile = blockIdx.y * gridDim.x + blockIdx.x;   // < 64
            stats[((long)b * 64 + tile) * 2 + 0] = S;
            stats[((long)b * 64 + tile) * 2 + 1] = SS;
        }
    }
}

// --------------------- fp32 -> fp16 convert pass ----------------------------
__global__ __launch_bounds__(256)
void conv_half(const float* __restrict__ in, __half* __restrict__ out, int n4)
{
    int i = blockIdx.x * 256 + threadIdx.x;
    if (i >= n4) return;
    float4 v = ((const float4*)in)[i];
    ((__half2*)out)[2 * i]     = __floats2half2_rn(v.x, v.y);
    ((__half2*)out)[2 * i + 1] = __floats2half2_rn(v.z, v.w);
}

// --------------------- softmax over time dim (k), fp16 in/out ---------------
__global__ __launch_bounds__(256)
void softmax_k(__half* __restrict__ kh)
{
    __shared__ float sm[32];
    int r = blockIdx.x;              // b*512 + c
    int b = r >> 9, c = r & 511;
    __half2* row = (__half2*)(kh + ((long)b * HID + c) * T);
    int tid = threadIdx.x;

    float v[16];
    float mx = -1e30f;
    #pragma unroll
    for (int i = 0; i < 8; i++) {
        float2 f = __half22float2(row[tid + i * 256]);
        v[2 * i] = f.x; v[2 * i + 1] = f.y;
        mx = fmaxf(mx, fmaxf(f.x, f.y));
    }
    mx = blockReduceMax(mx, sm);
    float s = 0.f;
    #pragma unroll
    for (int i = 0; i < 16; i++) { v[i] = __expf(v[i] - mx); s += v[i]; }
    s = blockReduceSum(s, sm);
    float inv = 1.f / s;
    #pragma unroll
    for (int i = 0; i < 8; i++)
        row[tid + i * 256] = __floats2half2_rn(v[2 * i] * inv, v[2 * i + 1] * inv);
}

// --------------------- context partial: k @ v^T (split-K over t) ------------
__global__ __launch_bounds__(256)
void ctx_partial(const __half* __restrict__ kh, const __half* __restrict__ vh,
                 float* __restrict__ part)
{
    __shared__ float ks[32][65];
    __shared__ float vs[32][65];
    int s = blockIdx.x, bh = blockIdx.y;
    int b = bh >> 3, h = bh & 7;
    const __half* kbase = kh + (long)b * HID * T + (long)(h * DH) * T;
    const __half* vbase = vh + (long)b * HID * T + (long)(h * DH) * T;
    int tid = threadIdx.x, tx = tid & 15, ty = tid >> 4;

    float acc[4][4] = {};
    for (int t0 = s * 512; t0 < s * 512 + 512; t0 += 32) {
        #pragma unroll
        for (int i = 0; i < 8; i++) {
            int v = tid + i * 256;
            int d = v >> 5, tl = v & 31;
            ks[tl][d] = __half2float(kbase[(long)d * T + t0 + tl]);
            vs[tl][d] = __half2float(vbase[(long)d * T + t0 + tl]);
        }
        __syncthreads();
        #pragma unroll
        for (int tl = 0; tl < 32; tl++) {
            float a[4], bb[4];
            #pragma unroll
            for (int i = 0; i < 4; i++) a[i]  = ks[tl][ty * 4 + i];
            #pragma unroll
            for (int j = 0; j < 4; j++) bb[j] = vs[tl][tx * 4 + j];
            #pragma unroll
            for (int i = 0; i < 4; i++)
                #pragma unroll
                for (int j = 0; j < 4; j++)
                    acc[i][j] = fmaf(a[i], bb[j], acc[i][j]);
        }
        __syncthreads();
    }
    float* p = part + ((long)bh * 8 + s) * (DH * DH);
    #pragma unroll
    for (int i = 0; i < 4; i++)
        #pragma unroll
        for (int j = 0; j < 4; j++)
            p[(ty * 4 + i) * DH + tx * 4 + j] = acc[i][j];
}

__global__ __launch_bounds__(256)
void ctx_reduce(const float* __restrict__ part, float* __restrict__ ctx)
{
    int bh = blockIdx.x;
    long base = (long)bh * 8 * (DH * DH);
    for (int i = threadIdx.x; i < DH * DH; i += 256) {
        float s = 0.f;
        #pragma unroll
        for (int sp = 0; sp < 8; sp++) s += part[base + (long)sp * (DH * DH) + i];
        ctx[(long)bh * (DH * DH) + i] = s;
    }
}

// ----- Weff[b][o][h*64+d] = sum_e Wout[o][h*64+e] * ctx[b][h][d][e] -> half --
__global__ __launch_bounds__(256)
void make_weff(const float* __restrict__ ctx, const float* __restrict__ Wout,
               __half* __restrict__ weffh)
{
    __shared__ float cs[DH][DH];   // ctx[d][e]
    int b = blockIdx.x, h = blockIdx.y;
    const float* c = ctx + (long)(b * H + h) * (DH * DH);
    for (int i = threadIdx.x; i < DH * DH; i += 256) cs[i >> 6][i & 63] = c[i];
    __syncthreads();

    #pragma unroll
    for (int oo = 0; oo < 2; oo++) {
        int o = threadIdx.x + oo * 256;
        float w[DH];
        #pragma unroll
        for (int e = 0; e < DH; e++) w[e] = Wout[(long)o * C + h * DH + e];
        for (int d = 0; d < DH; d++) {
            float s = 0.f;
            #pragma unroll
            for (int e = 0; e < DH; e++) s = fmaf(w[e], cs[d][e], s);
            weffh[((long)b * C + o) * C + h * DH + d] = __float2half(s);
        }
    }
}

// --------------------- GroupNorm finalize + normalize -----------------------
__global__ __launch_bounds__(64)
void gn_finalize(const float* __restrict__ stats, float* __restrict__ mr)
{
    __shared__ float sm[32];
    int b = blockIdx.x;
    float s  = stats[(b * 64 + threadIdx.x) * 2 + 0];
    float ss = stats[(b * 64 + threadIdx.x) * 2 + 1];
    float S  = blockReduceSum(s, sm);
    float SS = blockReduceSum(ss, sm);
    if (threadIdx.x == 0) {
        const float n = (float)((long)C * T);
        float mean = S / n;
        float var  = SS / n - mean * mean;
        mr[b * 2 + 0] = mean;
        mr[b * 2 + 1] = rsqrtf(var + GN_EPS);
    }
}

__global__ __launch_bounds__(256)
void gn_norm(const float* __restrict__ y, const float* __restrict__ mr,
             const float* __restrict__ gw, const float* __restrict__ gb,
             float* __restrict__ out)
{
    int b = blockIdx.y;
    long base = (long)b * C * T;
    int idx = (blockIdx.x * 256 + threadIdx.x) * 4;
    int c = idx >> 12;                 // / 4096
    float mean = mr[b * 2 + 0], rstd = mr[b * 2 + 1];
    float g   = gw[c] * rstd;
    float beta = gb[c] - mean * g;
    float4 v = *(const float4*)&y[base + idx];
    v.x = fmaf(v.x, g, beta);
    v.y = fmaf(v.y, g, beta);
    v.z = fmaf(v.z, g, beta);
    v.w = fmaf(v.w, g, beta);
    *(float4*)&out[base + idx] = v;
}

// ---------------------------------------------------------------------------
extern "C" void kernel_launch(void* const* d_in, const int* in_sizes, int n_in,
                              void* d_out, int out_size)
{
    const float* x     = (const float*)d_in[0];
    const float* Wqkv  = (const float*)d_in[1];
    const float* Wout  = (const float*)d_in[2];
    const float* bout  = (const float*)d_in[3];
    const float* gnw   = (const float*)d_in[4];
    const float* gnb   = (const float*)d_in[5];
    float* out = (float*)d_out;

    float *y, *part, *ctx, *stats, *mr;
    __half *xh, *qh, *kh, *vh, *wqkvh, *weffh;
    cudaGetSymbolAddress((void**)&y,     g_y);
    cudaGetSymbolAddress((void**)&part,  g_ctx_part);
    cudaGetSymbolAddress((void**)&ctx,   g_ctx);
    cudaGetSymbolAddress((void**)&stats, g_stats);
    cudaGetSymbolAddress((void**)&mr,    g_mr);
    cudaGetSymbolAddress((void**)&xh,    g_xh);
    cudaGetSymbolAddress((void**)&qh,    g_qh);
    cudaGetSymbolAddress((void**)&kh,    g_kh);
    cudaGetSymbolAddress((void**)&vh,    g_vh);
    cudaGetSymbolAddress((void**)&wqkvh, g_wqkvh);
    cudaGetSymbolAddress((void**)&weffh, g_weffh);

    cudaFuncSetAttribute(hgemm<1>,
                         cudaFuncAttributeMaxDynamicSharedMemorySize, TGEMM_SMEM);
    cudaFuncSetAttribute(hgemm<2>,
                         cudaFuncAttributeMaxDynamicSharedMemorySize, TGEMM_SMEM);

    // 0) convert inputs to fp16
    conv_half<<<(B * C * T / 4 + 255) / 256, 256>>>(x, xh, B * C * T / 4);
    conv_half<<<(QKV_CH * C / 4 + 255) / 256, 256>>>(Wqkv, wqkvh, QKV_CH * C / 4);

    // 1) qkv GEMM + fused softmax_q / fp16 conversion
    hgemm<1><<<dim3(T / BN, QKV_CH / BM, B), 256, TGEMM_SMEM>>>(
        wqkvh, 0L, xh, (long)C * T, nullptr, 0L,
        QKV_CH, T, C, nullptr, qh, kh, vh, nullptr);

    // 2) softmax over time for k (fp16 in/out)
    softmax_k<<<B * HID, 256>>>(kh);

    // 3) context = k @ v^T  (split-K 8) then reduce
    ctx_partial<<<dim3(8, B * H), 256>>>(kh, vh, part);
    ctx_reduce<<<B * H, 256>>>(part, ctx);

    // 4) fold Wout with context -> half
    make_weff<<<dim3(B, H), 256>>>(ctx, Wout, weffh);

    // 5) y = Weff @ q + b_out, fused GN partial stats
    hgemm<2><<<dim3(T / BN, C / BM, B), 256, TGEMM_SMEM>>>(
        weffh, (long)C * C, qh, (long)HID * T, y, (long)C * T,
        C, T, C, bout, nullptr, nullptr, nullptr, stats);

    // 6) GroupNorm finalize + apply
    gn_finalize<<<B, 64>>>(stats, mr);
    gn_norm<<<dim3((C * T) / 1024, B), 256>>>(y, mr, gnw, gnb, out);
}

// round 11
// speedup vs baseline: 4.4398x; 1.1703x over previous
#include <cuda_runtime.h>
#include <cuda_fp16.h>
#include <cstdint>

// ---------------------------------------------------------------------------
// LinearAttention fused pipeline (fp16 HMMA GEMMs + HMMA ctx, fused softmax_q
// + GN stats). b=16, c=512, t=4096, heads=8, dh=64, hidden=512
// ---------------------------------------------------------------------------

#define B   16
#define C   512
#define T   4096
#define H   8
#define DH  64
#define HID 512
#define QKV_CH 1536
#define SCALE 0.125f   // 64^-0.5
#define GN_EPS 1e-5f

// Scratch (static device arrays: allocation-free rule)
__device__ float  g_y[(size_t)B * C * T];                 // 134 MB
__device__ __half g_xh[(size_t)B * C * T];                // 67 MB
__device__ __half g_qh[(size_t)B * HID * T];              // 67 MB (softmaxed q)
__device__ __half g_kh[(size_t)B * HID * T];              // 67 MB
__device__ __half g_vh[(size_t)B * HID * T];              // 67 MB
__device__ __half g_wqkvh[(size_t)QKV_CH * C];            // 1.5 MB
__device__ __half g_weffh[(size_t)B * C * C];             // 8 MB
__device__ float  g_ctx[(size_t)B * H * DH * DH];         // 2 MB
__device__ float  g_stats[B * 64 * 2];
__device__ float  g_mr[B * 2];

// ========================= helpers =========================================
__device__ __forceinline__ uint32_t smem_u32(const void* p) {
    uint32_t a;
    asm("{ .reg .u64 t; cvta.to.shared.u64 t, %1; cvt.u32.u64 %0, t; }"
        : "=r"(a) : "l"(p));
    return a;
}

__device__ __forceinline__ void cp_async16(uint32_t smem_dst, const void* gsrc) {
    asm volatile("cp.async.cg.shared.global [%0], [%1], 16;"
                 :: "r"(smem_dst), "l"(gsrc));
}
__device__ __forceinline__ void cp_commit() {
    asm volatile("cp.async.commit_group;" ::: "memory");
}
template <int N>
__device__ __forceinline__ void cp_wait() {
    asm volatile("cp.async.wait_group %0;" :: "n"(N) : "memory");
}

__device__ __forceinline__ void ldsm_x4(uint32_t* r, uint32_t addr) {
    asm volatile("ldmatrix.sync.aligned.m8n8.x4.shared.b16 {%0,%1,%2,%3}, [%4];"
                 : "=r"(r[0]), "=r"(r[1]), "=r"(r[2]), "=r"(r[3]) : "r"(addr));
}
__device__ __forceinline__ void ldsm_x4_trans(uint32_t* r, uint32_t addr) {
    asm volatile("ldmatrix.sync.aligned.m8n8.x4.trans.shared.b16 {%0,%1,%2,%3}, [%4];"
                 : "=r"(r[0]), "=r"(r[1]), "=r"(r[2]), "=r"(r[3]) : "r"(addr));
}

__device__ __forceinline__ void mma16n8k16(float* c, const uint32_t* a,
                                           const uint32_t* b) {
    asm volatile(
        "mma.sync.aligned.m16n8k16.row.col.f32.f16.f16.f32 "
        "{%0,%1,%2,%3}, {%4,%5,%6,%7}, {%8,%9}, {%0,%1,%2,%3};"
        : "+f"(c[0]), "+f"(c[1]), "+f"(c[2]), "+f"(c[3])
        : "r"(a[0]), "r"(a[1]), "r"(a[2]), "r"(a[3]),
          "r"(b[0]), "r"(b[1]));
}

// ------------------------- block reduce helper -----------------------------
__device__ __forceinline__ float blockReduceSum(float v, float* sm) {
    __syncthreads();
    #pragma unroll
    for (int o = 16; o; o >>= 1) v += __shfl_down_sync(0xffffffffu, v, o);
    int lane = threadIdx.x & 31, w = threadIdx.x >> 5;
    if (lane == 0) sm[w] = v;
    __syncthreads();
    if (w == 0) {
        v = (lane < (int)(blockDim.x >> 5)) ? sm[lane] : 0.f;
        #pragma unroll
        for (int o = 16; o; o >>= 1) v += __shfl_down_sync(0xffffffffu, v, o);
        if (lane == 0) sm[0] = v;
    }
    __syncthreads();
    return sm[0];
}

__device__ __forceinline__ float blockReduceMax(float v, float* sm) {
    __syncthreads();
    #pragma unroll
    for (int o = 16; o; o >>= 1) v = fmaxf(v, __shfl_down_sync(0xffffffffu, v, o));
    int lane = threadIdx.x & 31, w = threadIdx.x >> 5;
    if (lane == 0) sm[w] = v;
    __syncthreads();
    if (w == 0) {
        v = (lane < (int)(blockDim.x >> 5)) ? sm[lane] : -1e30f;
        #pragma unroll
        for (int o = 16; o; o >>= 1) v = fmaxf(v, __shfl_down_sync(0xffffffffu, v, o));
        if (lane == 0) sm[0] = v;
    }
    __syncthreads();
    return sm[0];
}

// ========================= fp16 HMMA GEMM ==================================
#define BM 128
#define BN 256
#define BK 32
#define ASH 40
#define BSH 264
#define A_BYTES (BM * ASH * 2)
#define B_BYTES (BK * BSH * 2)
#define STAGE_BYTES (A_BYTES + B_BYTES)   // 27136
#define NSTAGE 4
#define TGEMM_SMEM (NSTAGE * STAGE_BYTES) // 108544

template <int MODE>
__global__ __launch_bounds__(256, 1)
void hgemm(const __half* __restrict__ A, long strideA,
           const __half* __restrict__ X, long strideX,
           float* __restrict__ Y, long strideY,
           int M, int N, int K, const float* __restrict__ bias,
           __half* __restrict__ q_out, __half* __restrict__ k_out,
           __half* __restrict__ v_out, float* __restrict__ stats)
{
    extern __shared__ char dsm[];
    __shared__ float redsm[32];
    const int tid = threadIdx.x;
    const int wid = tid >> 5;
    const int lane = tid & 31;
    const int gid = lane >> 2;
    const int tg  = lane & 3;
    const int lg  = lane >> 3;
    const int lr  = lane & 7;
    const int b  = blockIdx.z;
    const int bm = blockIdx.y * BM, bn = blockIdx.x * BN;
    const __half* Ab = A + (long)b * strideA + (long)bm * K;
    const __half* Xb = X + (long)b * strideX + bn;

    const uint32_t smem0 = smem_u32(dsm);
    const int warpM = (wid >> 2) * 64;
    const int warpN = (wid & 3) * 64;

    const uint32_t a_ldsm = (uint32_t)(((warpM + (lg & 1) * 8 + lr) * ASH
                                        + (lg >> 1) * 8) * 2);
    const uint32_t b_ldsm = (uint32_t)A_BYTES
        + (uint32_t)((((lg & 1) * 8 + lr) * BSH + warpN + (lg >> 1) * 8) * 2);

    float acc[4][8][4];
    #pragma unroll
    for (int mt = 0; mt < 4; mt++)
        #pragma unroll
        for (int nt = 0; nt < 8; nt++)
            #pragma unroll
            for (int r = 0; r < 4; r++) acc[mt][nt][r] = 0.f;

    const int niter = K / BK;   // 16

    auto load_stage = [&](int it) {
        const int k0 = it * BK;
        const uint32_t sb = smem0 + (it % NSTAGE) * STAGE_BYTES;
        #pragma unroll
        for (int i = 0; i < 2; i++) {
            int v = tid + i * 256;
            int row = v >> 2, c8 = (v & 3) * 8;
            cp_async16(sb + (uint32_t)((row * ASH + c8) * 2),
                       &Ab[(long)row * K + k0 + c8]);
        }
        #pragma unroll
        for (int i = 0; i < 4; i++) {
            int v = tid + i * 256;
            int kr = v >> 5, c8 = (v & 31) * 8;
            cp_async16(sb + (uint32_t)A_BYTES + (uint32_t)((kr * BSH + c8) * 2),
                       &Xb[(long)(k0 + kr) * N + c8]);
        }
        cp_commit();
    };

    load_stage(0);
    load_stage(1);
    load_stage(2);

    for (int it = 0; it < niter; it++) {
        if (it + 3 < niter) { load_stage(it + 3); cp_wait<3>(); }
        else {
            int rem = niter - 1 - it;
            if (rem >= 3) cp_wait<3>();
            else if (rem == 2) cp_wait<2>();
            else if (rem == 1) cp_wait<1>();
            else cp_wait<0>();
        }
        __syncthreads();

        const uint32_t sb = smem0 + (it % NSTAGE) * STAGE_BYTES;

        #pragma unroll
        for (int kk = 0; kk < 2; kk++) {
            uint32_t afr[4][4], bfr[8][2];
            #pragma unroll
            for (int mt = 0; mt < 4; mt++)
                ldsm_x4(afr[mt], sb + a_ldsm
                        + (uint32_t)((mt * 16 * ASH + kk * 16) * 2));
            #pragma unroll
            for (int p = 0; p < 4; p++) {
                uint32_t r4[4];
                ldsm_x4_trans(r4, sb + b_ldsm
                              + (uint32_t)((kk * 16 * BSH + p * 16) * 2));
                bfr[2 * p][0] = r4[0]; bfr[2 * p][1] = r4[1];
                bfr[2 * p + 1][0] = r4[2]; bfr[2 * p + 1][1] = r4[3];
            }
            #pragma unroll
            for (int mt = 0; mt < 4; mt++)
                #pragma unroll
                for (int nt = 0; nt < 8; nt++)
                    mma16n8k16(acc[mt][nt], afr[mt], bfr[nt]);
        }
        __syncthreads();
    }

    if (MODE == 1) {
        const int ch0 = bm + warpM;
        if (ch0 < HID) {
            float mxA[8], mxB[8], scA[8], scB[8];
            #pragma unroll
            for (int nt = 0; nt < 8; nt++) {
                float a = -1e30f, bb = -1e30f;
                #pragma unroll
                for (int mt = 0; mt < 4; mt++) {
                    a  = fmaxf(a,  fmaxf(acc[mt][nt][0], acc[mt][nt][2]));
                    bb = fmaxf(bb, fmaxf(acc[mt][nt][1], acc[mt][nt][3]));
                }
                #pragma unroll
                for (int o = 4; o <= 16; o <<= 1) {
                    a  = fmaxf(a,  __shfl_xor_sync(0xffffffffu, a, o));
                    bb = fmaxf(bb, __shfl_xor_sync(0xffffffffu, bb, o));
                }
                mxA[nt] = a; mxB[nt] = bb;
            }
            #pragma unroll
            for (int nt = 0; nt < 8; nt++) {
                float sa = 0.f, sb2 = 0.f;
                #pragma unroll
                for (int mt = 0; mt < 4; mt++) {
                    acc[mt][nt][0] = __expf(acc[mt][nt][0] - mxA[nt]);
                    acc[mt][nt][2] = __expf(acc[mt][nt][2] - mxA[nt]);
                    sa += acc[mt][nt][0] + acc[mt][nt][2];
                    acc[mt][nt][1] = __expf(acc[mt][nt][1] - mxB[nt]);
                    acc[mt][nt][3] = __expf(acc[mt][nt][3] - mxB[nt]);
                    sb2 += acc[mt][nt][1] + acc[mt][nt][3];
                }
                #pragma unroll
                for (int o = 4; o <= 16; o <<= 1) {
                    sa  += __shfl_xor_sync(0xffffffffu, sa, o);
                    sb2 += __shfl_xor_sync(0xffffffffu, sb2, o);
                }
                scA[nt] = SCALE / sa; scB[nt] = SCALE / sb2;
            }
            __half* qb = q_out + (long)b * HID * T;
            #pragma unroll
            for (int mt = 0; mt < 4; mt++) {
                int ch = ch0 + mt * 16 + gid;
                #pragma unroll
                for (int nt = 0; nt < 8; nt++) {
                    int t = bn + warpN + nt * 8 + tg * 2;
                    *(__half2*)&qb[(long)ch * T + t] =
                        __floats2half2_rn(acc[mt][nt][0] * scA[nt],
                                          acc[mt][nt][1] * scB[nt]);
                    *(__half2*)&qb[(long)(ch + 8) * T + t] =
                        __floats2half2_rn(acc[mt][nt][2] * scA[nt],
                                          acc[mt][nt][3] * scB[nt]);
                }
            }
        } else {
            __half* dst = (ch0 < 2 * HID) ? k_out : v_out;
            const int chbase = ch0 - ((ch0 < 2 * HID) ? HID : 2 * HID);
            __half* db = dst + (long)b * HID * T;
            #pragma unroll
            for (int mt = 0; mt < 4; mt++) {
                int ch = chbase + mt * 16 + gid;
                #pragma unroll
                for (int nt = 0; nt < 8; nt++) {
                    int t = bn + warpN + nt * 8 + tg * 2;
                    *(__half2*)&db[(long)ch * T + t] =
                        __floats2half2_rn(acc[mt][nt][0], acc[mt][nt][1]);
                    *(__half2*)&db[(long)(ch + 8) * T + t] =
                        __floats2half2_rn(acc[mt][nt][2], acc[mt][nt][3]);
                }
            }
        }
    } else {
        float ls = 0.f, lss = 0.f;
        float* Yb = Y + (long)b * strideY;
        #pragma unroll
        for (int mt = 0; mt < 4; mt++) {
            int row0 = bm + warpM + mt * 16 + gid;
            float bv0 = bias[row0];
            float bv1 = bias[row0 + 8];
            #pragma unroll
            for (int nt = 0; nt < 8; nt++) {
                int col = bn + warpN + nt * 8 + tg * 2;
                float2 o0, o1;
                o0.x = acc[mt][nt][0] + bv0; o0.y = acc[mt][nt][1] + bv0;
                o1.x = acc[mt][nt][2] + bv1; o1.y = acc[mt][nt][3] + bv1;
                ls  += o0.x + o0.y + o1.x + o1.y;
                lss += o0.x * o0.x + o0.y * o0.y + o1.x * o1.x + o1.y * o1.y;
                *(float2*)&Yb[(long)row0 * N + col] = o0;
                *(float2*)&Yb[(long)(row0 + 8) * N + col] = o1;
            }
        }
        float S  = blockReduceSum(ls, redsm);
        float SS = blockReduceSum(lss, redsm);
        if (tid == 0) {
            int tile = blockIdx.y * gridDim.x + blockIdx.x;   // < 64
            stats[((long)b * 64 + tile) * 2 + 0] = S;
            stats[((long)b * 64 + tile) * 2 + 1] = SS;
        }
    }
}

// ================= HMMA context: ctx[b,h] = k @ v^T (64x64) ================
// One block per (b,h); 8 warps tiled 2(m)x4(n), each warp 32x16 of the output,
// accumulating over full t=4096 via m16n8k16. K rows = A row-major [d][t],
// V rows = B col-major [e][t] (non-trans ldmatrix). 4-stage cp.async, 64-t chunks.
#define CT 64
#define CROW 72                            // halves per row (64 + 8 pad)
#define CTILE_BYTES (DH * CROW * 2)        // 9216 per matrix
#define CSTAGE_BYTES (2 * CTILE_BYTES)     // 18432 (K + V)
#define CSTAGES 4
#define CTX_SMEM (CSTAGES * CSTAGE_BYTES)  // 73728

__global__ __launch_bounds__(256, 1)
void ctx_hmma(const __half* __restrict__ kh, const __half* __restrict__ vh,
              float* __restrict__ ctx)
{
    extern __shared__ char dsm[];
    const int tid = threadIdx.x;
    const int wid = tid >> 5;
    const int lane = tid & 31;
    const int gid = lane >> 2;
    const int tg  = lane & 3;
    const int lg  = lane >> 3;
    const int lr  = lane & 7;
    const int bh = blockIdx.x;
    const int b = bh >> 3, h = bh & 7;
    const __half* kb = kh + ((long)b * HID + h * DH) * T;
    const __half* vb = vh + ((long)b * HID + h * DH) * T;

    const uint32_t smem0 = smem_u32(dsm);
    const int warpM = (wid >> 2) * 32;     // 0 or 32
    const int warpN = (wid & 3) * 16;      // 0,16,32,48

    // A ldmatrix (K): octets = {m0-7 k0, m8-15 k0, m0-7 k8, m8-15 k8}
    const uint32_t a_base = (uint32_t)(((warpM + (lg & 1) * 8 + lr) * CROW
                                        + (lg >> 1) * 8) * 2);
    // B ldmatrix (V, non-trans): octets = {n0-7 k0, n0-7 k8, n8-15 k0, n8-15 k8}
    const int brow = warpN + (lane & 7) + ((lane >> 4) << 3);
    const uint32_t b_base = (uint32_t)CTILE_BYTES
        + (uint32_t)((brow * CROW + ((lane >> 3) & 1) * 8) * 2);

    float acc[2][2][4];
    #pragma unroll
    for (int mi = 0; mi < 2; mi++)
        #pragma unroll
        for (int ni = 0; ni < 2; ni++)
            #pragma unroll
            for (int r = 0; r < 4; r++) acc[mi][ni][r] = 0.f;

    const int nchunks = T / CT;            // 64

    auto load = [&](int ch) {
        const int t0 = ch * CT;
        const uint32_t sb = smem0 + (ch % CSTAGES) * CSTAGE_BYTES;
        #pragma unroll
        for (int i = 0; i < 4; i++) {
            int v = tid + i * 256;         // 0..1023
            int mat = v >> 9;              // 0=K, 1=V
            int r = (v >> 3) & 63;
            int c8 = (v & 7) * 8;
            const __half* gp = (mat ? vb : kb) + (long)r * T + t0 + c8;
            cp_async16(sb + (uint32_t)(mat * CTILE_BYTES + r * (CROW * 2) + c8 * 2),
                       gp);
        }
        cp_commit();
    };

    load(0); load(1); load(2);

    for (int ch = 0; ch < nchunks; ch++) {
        if (ch + 3 < nchunks) { load(ch + 3); cp_wait<3>(); }
        else {
            int rem = nchunks - 1 - ch;
            if (rem == 2) cp_wait<2>();
            else if (rem == 1) cp_wait<1>();
            else if (rem == 0) cp_wait<0>();
            else cp_wait<3>();
        }
        __syncthreads();

        const uint32_t sb = smem0 + (ch % CSTAGES) * CSTAGE_BYTES;
        #pragma unroll
        for (int kk = 0; kk < 4; kk++) {   // 4 x k16 within the 64-t chunk
            uint32_t afr[2][4], bfr4[4];
            #pragma unroll
            for (int mi = 0; mi < 2; mi++)
                ldsm_x4(afr[mi], sb + a_base
                        + (uint32_t)((mi * 16 * CROW + kk * 16) * 2));
            ldsm_x4(bfr4, sb + b_base + (uint32_t)(kk * 16 * 2));
            // bfr4: r0,r1 = n0-7 {k0-7, k8-15}; r2,r3 = n8-15
            #pragma unroll
            for (int mi = 0; mi < 2; mi++) {
                mma16n8k16(acc[mi][0], afr[mi], &bfr4[0]);
                mma16n8k16(acc[mi][1], afr[mi], &bfr4[2]);
            }
        }
        __syncthreads();
    }

    float* cp = ctx + (long)bh * (DH * DH);
    #pragma unroll
    for (int mi = 0; mi < 2; mi++) {
        int d0 = warpM + mi * 16 + gid;
        #pragma unroll
        for (int ni = 0; ni < 2; ni++) {
            int e = warpN + ni * 8 + tg * 2;
            *(float2*)&cp[d0 * DH + e]       = make_float2(acc[mi][ni][0], acc[mi][ni][1]);
            *(float2*)&cp[(d0 + 8) * DH + e] = make_float2(acc[mi][ni][2], acc[mi][ni][3]);
        }
    }
}

// --------------------- fp32 -> fp16 convert pass ----------------------------
__global__ __launch_bounds__(256)
void conv_half(const float* __restrict__ in, __half* __restrict__ out, int n4)
{
    int i = blockIdx.x * 256 + threadIdx.x;
    if (i >= n4) return;
    float4 v = ((const float4*)in)[i];
    ((__half2*)out)[2 * i]     = __floats2half2_rn(v.x, v.y);
    ((__half2*)out)[2 * i + 1] = __floats2half2_rn(v.z, v.w);
}

// --------------------- softmax over time dim (k), fp16 in/out ---------------
__global__ __launch_bounds__(256)
void softmax_k(__half* __restrict__ kh)
{
    __shared__ float sm[32];
    int r = blockIdx.x;              // b*512 + c
    int b = r >> 9, c = r & 511;
    __half2* row = (__half2*)(kh + ((long)b * HID + c) * T);
    int tid = threadIdx.x;

    float v[16];
    float mx = -1e30f;
    #pragma unroll
    for (int i = 0; i < 8; i++) {
        float2 f = __half22float2(row[tid + i * 256]);
        v[2 * i] = f.x; v[2 * i + 1] = f.y;
        mx = fmaxf(mx, fmaxf(f.x, f.y));
    }
    mx = blockReduceMax(mx, sm);
    float s = 0.f;
    #pragma unroll
    for (int i = 0; i < 16; i++) { v[i] = __expf(v[i] - mx); s += v[i]; }
    s = blockReduceSum(s, sm);
    float inv = 1.f / s;
    #pragma unroll
    for (int i = 0; i < 8; i++)
        row[tid + i * 256] = __floats2half2_rn(v[2 * i] * inv, v[2 * i + 1] * inv);
}

// ----- Weff[b][o][h*64+d] = sum_e Wout[o][h*64+e] * ctx[b][h][d][e] -> half --
__global__ __launch_bounds__(256)
void make_weff(const float* __restrict__ ctx, const float* __restrict__ Wout,
               __half* __restrict__ weffh)
{
    __shared__ float cs[DH][DH];   // ctx[d][e]
    int b = blockIdx.x, h = blockIdx.y;
    const float* c = ctx + (long)(b * H + h) * (DH * DH);
    for (int i = threadIdx.x; i < DH * DH; i += 256) cs[i >> 6][i & 63] = c[i];
    __syncthreads();

    #pragma unroll
    for (int oo = 0; oo < 2; oo++) {
        int o = threadIdx.x + oo * 256;
        float w[DH];
        #pragma unroll
        for (int e = 0; e < DH; e++) w[e] = Wout[(long)o * C + h * DH + e];
        for (int d = 0; d < DH; d++) {
            float s = 0.f;
            #pragma unroll
            for (int e = 0; e < DH; e++) s = fmaf(w[e], cs[d][e], s);
            weffh[((long)b * C + o) * C + h * DH + d] = __float2half(s);
        }
    }
}

// --------------------- GroupNorm finalize + normalize -----------------------
__global__ __launch_bounds__(64)
void gn_finalize(const float* __restrict__ stats, float* __restrict__ mr)
{
    __shared__ float sm[32];
    int b = blockIdx.x;
    float s  = stats[(b * 64 + threadIdx.x) * 2 + 0];
    float ss = stats[(b * 64 + threadIdx.x) * 2 + 1];
    float S  = blockReduceSum(s, sm);
    float SS = blockReduceSum(ss, sm);
    if (threadIdx.x == 0) {
        const float n = (float)((long)C * T);
        float mean = S / n;
        float var  = SS / n - mean * mean;
        mr[b * 2 + 0] = mean;
        mr[b * 2 + 1] = rsqrtf(var + GN_EPS);
    }
}

__global__ __launch_bounds__(256)
void gn_norm(const float* __restrict__ y, const float* __restrict__ mr,
             const float* __restrict__ gw, const float* __restrict__ gb,
             float* __restrict__ out)
{
    int b = blockIdx.y;
    long base = (long)b * C * T;
    int idx = (blockIdx.x * 256 + threadIdx.x) * 4;
    int c = idx >> 12;                 // / 4096
    float mean = mr[b * 2 + 0], rstd = mr[b * 2 + 1];
    float g   = gw[c] * rstd;
    float beta = gb[c] - mean * g;
    float4 v = *(const float4*)&y[base + idx];
    v.x = fmaf(v.x, g, beta);
    v.y = fmaf(v.y, g, beta);
    v.z = fmaf(v.z, g, beta);
    v.w = fmaf(v.w, g, beta);
    *(float4*)&out[base + idx] = v;
}

// ---------------------------------------------------------------------------
extern "C" void kernel_launch(void* const* d_in, const int* in_sizes, int n_in,
                              void* d_out, int out_size)
{
    const float* x     = (const float*)d_in[0];
    const float* Wqkv  = (const float*)d_in[1];
    const float* Wout  = (const float*)d_in[2];
    const float* bout  = (const float*)d_in[3];
    const float* gnw   = (const float*)d_in[4];
    const float* gnb   = (const float*)d_in[5];
    float* out = (float*)d_out;

    float *y, *ctx, *stats, *mr;
    __half *xh, *qh, *kh, *vh, *wqkvh, *weffh;
    cudaGetSymbolAddress((void**)&y,     g_y);
    cudaGetSymbolAddress((void**)&ctx,   g_ctx);
    cudaGetSymbolAddress((void**)&stats, g_stats);
    cudaGetSymbolAddress((void**)&mr,    g_mr);
    cudaGetSymbolAddress((void**)&xh,    g_xh);
    cudaGetSymbolAddress((void**)&qh,    g_qh);
    cudaGetSymbolAddress((void**)&kh,    g_kh);
    cudaGetSymbolAddress((void**)&vh,    g_vh);
    cudaGetSymbolAddress((void**)&wqkvh, g_wqkvh);
    cudaGetSymbolAddress((void**)&weffh, g_weffh);

    cudaFuncSetAttribute(hgemm<1>,
                         cudaFuncAttributeMaxDynamicSharedMemorySize, TGEMM_SMEM);
    cudaFuncSetAttribute(hgemm<2>,
                         cudaFuncAttributeMaxDynamicSharedMemorySize, TGEMM_SMEM);
    cudaFuncSetAttribute(ctx_hmma,
                         cudaFuncAttributeMaxDynamicSharedMemorySize, CTX_SMEM);

    // 0) convert inputs to fp16
    conv_half<<<(B * C * T / 4 + 255) / 256, 256>>>(x, xh, B * C * T / 4);
    conv_half<<<(QKV_CH * C / 4 + 255) / 256, 256>>>(Wqkv, wqkvh, QKV_CH * C / 4);

    // 1) qkv GEMM + fused softmax_q / fp16 conversion
    hgemm<1><<<dim3(T / BN, QKV_CH / BM, B), 256, TGEMM_SMEM>>>(
        wqkvh, 0L, xh, (long)C * T, nullptr, 0L,
        QKV_CH, T, C, nullptr, qh, kh, vh, nullptr);

    // 2) softmax over time for k (fp16 in/out)
    softmax_k<<<B * HID, 256>>>(kh);

    // 3) ctx = k @ v^T per (b,h) via HMMA
    ctx_hmma<<<B * H, 256, CTX_SMEM>>>(kh, vh, ctx);

    // 4) fold Wout with context -> half
    make_weff<<<dim3(B, H), 256>>>(ctx, Wout, weffh);

    // 5) y = Weff @ q + b_out, fused GN partial stats
    hgemm<2><<<dim3(T / BN, C / BM, B), 256, TGEMM_SMEM>>>(
        weffh, (long)C * C, qh, (long)HID * T, y, (long)C * T,
        C, T, C, bout, nullptr, nullptr, nullptr, stats);

    // 6) GroupNorm finalize + apply
    gn_finalize<<<B, 64>>>(stats, mr);
    gn_norm<<<dim3((C * T) / 1024, B), 256>>>(y, mr, gnw, gnb, out);
}

// round 12
// speedup vs baseline: 4.4991x; 1.0134x over previous
#include <cuda_runtime.h>
#include <cuda_fp16.h>
#include <cstdint>

// ---------------------------------------------------------------------------
// LinearAttention fused pipeline (fp16 HMMA GEMMs + HMMA ctx, fused softmax_q
// + GN stats; stream-forked GEMM1_q || softmax_k->ctx->weff chain).
// b=16, c=512, t=4096, heads=8, dh=64, hidden=512
// ---------------------------------------------------------------------------

#define B   16
#define C   512
#define T   4096
#define H   8
#define DH  64
#define HID 512
#define QKV_CH 1536
#define SCALE 0.125f   // 64^-0.5
#define GN_EPS 1e-5f

// Scratch (static device arrays: allocation-free rule)
__device__ __half g_xh[(size_t)B * C * T];                // 67 MB (xh, then y fp16)
__device__ __half g_qh[(size_t)B * HID * T];              // 67 MB (softmaxed q)
__device__ __half g_kh[(size_t)B * HID * T];              // 67 MB
__device__ __half g_vh[(size_t)B * HID * T];              // 67 MB
__device__ __half g_wqkvh[(size_t)QKV_CH * C];            // 1.5 MB
__device__ __half g_weffh[(size_t)B * C * C];             // 8 MB
__device__ float  g_ctx[(size_t)B * H * DH * DH];         // 2 MB
__device__ float  g_stats[B * 64 * 2];
__device__ float  g_mr[B * 2];

// ========================= helpers =========================================
__device__ __forceinline__ uint32_t smem_u32(const void* p) {
    uint32_t a;
    asm("{ .reg .u64 t; cvta.to.shared.u64 t, %1; cvt.u32.u64 %0, t; }"
        : "=r"(a) : "l"(p));
    return a;
}

__device__ __forceinline__ void cp_async16(uint32_t smem_dst, const void* gsrc) {
    asm volatile("cp.async.cg.shared.global [%0], [%1], 16;"
                 :: "r"(smem_dst), "l"(gsrc));
}
__device__ __forceinline__ void cp_commit() {
    asm volatile("cp.async.commit_group;" ::: "memory");
}
template <int N>
__device__ __forceinline__ void cp_wait() {
    asm volatile("cp.async.wait_group %0;" :: "n"(N) : "memory");
}

__device__ __forceinline__ void ldsm_x4(uint32_t* r, uint32_t addr) {
    asm volatile("ldmatrix.sync.aligned.m8n8.x4.shared.b16 {%0,%1,%2,%3}, [%4];"
                 : "=r"(r[0]), "=r"(r[1]), "=r"(r[2]), "=r"(r[3]) : "r"(addr));
}
__device__ __forceinline__ void ldsm_x4_trans(uint32_t* r, uint32_t addr) {
    asm volatile("ldmatrix.sync.aligned.m8n8.x4.trans.shared.b16 {%0,%1,%2,%3}, [%4];"
                 : "=r"(r[0]), "=r"(r[1]), "=r"(r[2]), "=r"(r[3]) : "r"(addr));
}

__device__ __forceinline__ void mma16n8k16(float* c, const uint32_t* a,
                                           const uint32_t* b) {
    asm volatile(
        "mma.sync.aligned.m16n8k16.row.col.f32.f16.f16.f32 "
        "{%0,%1,%2,%3}, {%4,%5,%6,%7}, {%8,%9}, {%0,%1,%2,%3};"
        : "+f"(c[0]), "+f"(c[1]), "+f"(c[2]), "+f"(c[3])
        : "r"(a[0]), "r"(a[1]), "r"(a[2]), "r"(a[3]),
          "r"(b[0]), "r"(b[1]));
}

// ------------------------- block reduce helper -----------------------------
__device__ __forceinline__ float blockReduceSum(float v, float* sm) {
    __syncthreads();
    #pragma unroll
    for (int o = 16; o; o >>= 1) v += __shfl_down_sync(0xffffffffu, v, o);
    int lane = threadIdx.x & 31, w = threadIdx.x >> 5;
    if (lane == 0) sm[w] = v;
    __syncthreads();
    if (w == 0) {
        v = (lane < (int)(blockDim.x >> 5)) ? sm[lane] : 0.f;
        #pragma unroll
        for (int o = 16; o; o >>= 1) v += __shfl_down_sync(0xffffffffu, v, o);
        if (lane == 0) sm[0] = v;
    }
    __syncthreads();
    return sm[0];
}

__device__ __forceinline__ float blockReduceMax(float v, float* sm) {
    __syncthreads();
    #pragma unroll
    for (int o = 16; o; o >>= 1) v = fmaxf(v, __shfl_down_sync(0xffffffffu, v, o));
    int lane = threadIdx.x & 31, w = threadIdx.x >> 5;
    if (lane == 0) sm[w] = v;
    __syncthreads();
    if (w == 0) {
        v = (lane < (int)(blockDim.x >> 5)) ? sm[lane] : -1e30f;
        #pragma unroll
        for (int o = 16; o; o >>= 1) v = fmaxf(v, __shfl_down_sync(0xffffffffu, v, o));
        if (lane == 0) sm[0] = v;
    }
    __syncthreads();
    return sm[0];
}

// ========================= fp16 HMMA GEMM ==================================
#define BM 128
#define BN 256
#define BK 32
#define ASH 40
#define BSH 264
#define A_BYTES (BM * ASH * 2)
#define B_BYTES (BK * BSH * 2)
#define STAGE_BYTES (A_BYTES + B_BYTES)   // 27136
#define NSTAGE 4
#define TGEMM_SMEM (NSTAGE * STAGE_BYTES) // 108544

// MODE 1: qkv epilogue (q softmax -> qh, k/v -> kh/vh), rows offset by bm0.
// MODE 2: y fp16 -> q_out, bias, GN partial stats.
template <int MODE>
__global__ __launch_bounds__(256, 1)
void hgemm(const __half* __restrict__ A, long strideA,
           const __half* __restrict__ X, long strideX,
           int bm0,
           int M, int N, int K, const float* __restrict__ bias,
           __half* __restrict__ q_out, __half* __restrict__ k_out,
           __half* __restrict__ v_out, float* __restrict__ stats)
{
    extern __shared__ char dsm[];
    __shared__ float redsm[32];
    const int tid = threadIdx.x;
    const int wid = tid >> 5;
    const int lane = tid & 31;
    const int gid = lane >> 2;
    const int tg  = lane & 3;
    const int lg  = lane >> 3;
    const int lr  = lane & 7;
    const int b  = blockIdx.z;
    const int bm = bm0 + blockIdx.y * BM, bn = blockIdx.x * BN;
    const __half* Ab = A + (long)b * strideA + (long)bm * K;
    const __half* Xb = X + (long)b * strideX + bn;

    const uint32_t smem0 = smem_u32(dsm);
    const int warpM = (wid >> 2) * 64;
    const int warpN = (wid & 3) * 64;

    const uint32_t a_ldsm = (uint32_t)(((warpM + (lg & 1) * 8 + lr) * ASH
                                        + (lg >> 1) * 8) * 2);
    const uint32_t b_ldsm = (uint32_t)A_BYTES
        + (uint32_t)((((lg & 1) * 8 + lr) * BSH + warpN + (lg >> 1) * 8) * 2);

    float acc[4][8][4];
    #pragma unroll
    for (int mt = 0; mt < 4; mt++)
        #pragma unroll
        for (int nt = 0; nt < 8; nt++)
            #pragma unroll
            for (int r = 0; r < 4; r++) acc[mt][nt][r] = 0.f;

    const int niter = K / BK;   // 16

    auto load_stage = [&](int it) {
        const int k0 = it * BK;
        const uint32_t sb = smem0 + (it % NSTAGE) * STAGE_BYTES;
        #pragma unroll
        for (int i = 0; i < 2; i++) {
            int v = tid + i * 256;
            int row = v >> 2, c8 = (v & 3) * 8;
            cp_async16(sb + (uint32_t)((row * ASH + c8) * 2),
                       &Ab[(long)row * K + k0 + c8]);
        }
        #pragma unroll
        for (int i = 0; i < 4; i++) {
            int v = tid + i * 256;
            int kr = v >> 5, c8 = (v & 31) * 8;
            cp_async16(sb + (uint32_t)A_BYTES + (uint32_t)((kr * BSH + c8) * 2),
                       &Xb[(long)(k0 + kr) * N + c8]);
        }
        cp_commit();
    };

    load_stage(0);
    load_stage(1);
    load_stage(2);

    for (int it = 0; it < niter; it++) {
        if (it + 3 < niter) { load_stage(it + 3); cp_wait<3>(); }
        else {
            int rem = niter - 1 - it;
            if (rem >= 3) cp_wait<3>();
            else if (rem == 2) cp_wait<2>();
            else if (rem == 1) cp_wait<1>();
            else cp_wait<0>();
        }
        __syncthreads();

        const uint32_t sb = smem0 + (it % NSTAGE) * STAGE_BYTES;

        #pragma unroll
        for (int kk = 0; kk < 2; kk++) {
            uint32_t afr[4][4], bfr[8][2];
            #pragma unroll
            for (int mt = 0; mt < 4; mt++)
                ldsm_x4(afr[mt], sb + a_ldsm
                        + (uint32_t)((mt * 16 * ASH + kk * 16) * 2));
            #pragma unroll
            for (int p = 0; p < 4; p++) {
                uint32_t r4[4];
                ldsm_x4_trans(r4, sb + b_ldsm
                              + (uint32_t)((kk * 16 * BSH + p * 16) * 2));
                bfr[2 * p][0] = r4[0]; bfr[2 * p][1] = r4[1];
                bfr[2 * p + 1][0] = r4[2]; bfr[2 * p + 1][1] = r4[3];
            }
            #pragma unroll
            for (int mt = 0; mt < 4; mt++)
                #pragma unroll
                for (int nt = 0; nt < 8; nt++)
                    mma16n8k16(acc[mt][nt], afr[mt], bfr[nt]);
        }
        __syncthreads();
    }

    if (MODE == 1) {
        const int ch0 = bm + warpM;
        if (ch0 < HID) {
            float mxA[8], mxB[8], scA[8], scB[8];
            #pragma unroll
            for (int nt = 0; nt < 8; nt++) {
                float a = -1e30f, bb = -1e30f;
                #pragma unroll
                for (int mt = 0; mt < 4; mt++) {
                    a  = fmaxf(a,  fmaxf(acc[mt][nt][0], acc[mt][nt][2]));
                    bb = fmaxf(bb, fmaxf(acc[mt][nt][1], acc[mt][nt][3]));
                }
                #pragma unroll
                for (int o = 4; o <= 16; o <<= 1) {
                    a  = fmaxf(a,  __shfl_xor_sync(0xffffffffu, a, o));
                    bb = fmaxf(bb, __shfl_xor_sync(0xffffffffu, bb, o));
                }
                mxA[nt] = a; mxB[nt] = bb;
            }
            #pragma unroll
            for (int nt = 0; nt < 8; nt++) {
                float sa = 0.f, sb2 = 0.f;
                #pragma unroll
                for (int mt = 0; mt < 4; mt++) {
                    acc[mt][nt][0] = __expf(acc[mt][nt][0] - mxA[nt]);
                    acc[mt][nt][2] = __expf(acc[mt][nt][2] - mxA[nt]);
                    sa += acc[mt][nt][0] + acc[mt][nt][2];
                    acc[mt][nt][1] = __expf(acc[mt][nt][1] - mxB[nt]);
                    acc[mt][nt][3] = __expf(acc[mt][nt][3] - mxB[nt]);
                    sb2 += acc[mt][nt][1] + acc[mt][nt][3];
                }
                #pragma unroll
                for (int o = 4; o <= 16; o <<= 1) {
                    sa  += __shfl_xor_sync(0xffffffffu, sa, o);
                    sb2 += __shfl_xor_sync(0xffffffffu, sb2, o);
                }
                scA[nt] = SCALE / sa; scB[nt] = SCALE / sb2;
            }
            __half* qb = q_out + (long)b * HID * T;
            #pragma unroll
            for (int mt = 0; mt < 4; mt++) {
                int ch = ch0 + mt * 16 + gid;
                #pragma unroll
                for (int nt = 0; nt < 8; nt++) {
                    int t = bn + warpN + nt * 8 + tg * 2;
                    *(__half2*)&qb[(long)ch * T + t] =
                        __floats2half2_rn(acc[mt][nt][0] * scA[nt],
                                          acc[mt][nt][1] * scB[nt]);
                    *(__half2*)&qb[(long)(ch + 8) * T + t] =
                        __floats2half2_rn(acc[mt][nt][2] * scA[nt],
                                          acc[mt][nt][3] * scB[nt]);
                }
            }
        } else {
            __half* dst = (ch0 < 2 * HID) ? k_out : v_out;
            const int chbase = ch0 - ((ch0 < 2 * HID) ? HID : 2 * HID);
            __half* db = dst + (long)b * HID * T;
            #pragma unroll
            for (int mt = 0; mt < 4; mt++) {
                int ch = chbase + mt * 16 + gid;
                #pragma unroll
                for (int nt = 0; nt < 8; nt++) {
                    int t = bn + warpN + nt * 8 + tg * 2;
                    *(__half2*)&db[(long)ch * T + t] =
                        __floats2half2_rn(acc[mt][nt][0], acc[mt][nt][1]);
                    *(__half2*)&db[(long)(ch + 8) * T + t] =
                        __floats2half2_rn(acc[mt][nt][2], acc[mt][nt][3]);
                }
            }
        }
    } else {
        // ---- GEMM2 epilogue: y fp16 + bias, GN partial sums (fp32) ----
        float ls = 0.f, lss = 0.f;
        __half* yb = q_out + (long)b * C * T;
        #pragma unroll
        for (int mt = 0; mt < 4; mt++) {
            int row0 = bm + warpM + mt * 16 + gid;
            float bv0 = bias[row0];
            float bv1 = bias[row0 + 8];
            #pragma unroll
            for (int nt = 0; nt < 8; nt++) {
                int col = bn + warpN + nt * 8 + tg * 2;
                float o0x = acc[mt][nt][0] + bv0, o0y = acc[mt][nt][1] + bv0;
                float o1x = acc[mt][nt][2] + bv1, o1y = acc[mt][nt][3] + bv1;
                ls  += o0x + o0y + o1x + o1y;
                lss += o0x * o0x + o0y * o0y + o1x * o1x + o1y * o1y;
                *(__half2*)&yb[(long)row0 * T + col] = __floats2half2_rn(o0x, o0y);
                *(__half2*)&yb[(long)(row0 + 8) * T + col] = __floats2half2_rn(o1x, o1y);
            }
        }
        float S  = blockReduceSum(ls, redsm);
        float SS = blockReduceSum(lss, redsm);
        if (tid == 0) {
            int tile = blockIdx.y * gridDim.x + blockIdx.x;   // < 64
            stats[((long)b * 64 + tile) * 2 + 0] = S;
            stats[((long)b * 64 + tile) * 2 + 1] = SS;
        }
    }
}

// ================= HMMA context: ctx[b,h] = k @ v^T (64x64) ================
#define CT 64
#define CROW 72
#define CTILE_BYTES (DH * CROW * 2)        // 9216
#define CSTAGE_BYTES (2 * CTILE_BYTES)     // 18432
#define CSTAGES 4
#define CTX_SMEM (CSTAGES * CSTAGE_BYTES)  // 73728

__global__ __launch_bounds__(256, 1)
void ctx_hmma(const __half* __restrict__ kh, const __half* __restrict__ vh,
              float* __restrict__ ctx)
{
    extern __shared__ char dsm[];
    const int tid = threadIdx.x;
    const int wid = tid >> 5;
    const int lane = tid & 31;
    const int gid = lane >> 2;
    const int tg  = lane & 3;
    const int lg  = lane >> 3;
    const int lr  = lane & 7;
    const int bh = blockIdx.x;
    const int b = bh >> 3, h = bh & 7;
    const __half* kb = kh + ((long)b * HID + h * DH) * T;
    const __half* vb = vh + ((long)b * HID + h * DH) * T;

    const uint32_t smem0 = smem_u32(dsm);
    const int warpM = (wid >> 2) * 32;
    const int warpN = (wid & 3) * 16;

    const uint32_t a_base = (uint32_t)(((warpM + (lg & 1) * 8 + lr) * CROW
                                        + (lg >> 1) * 8) * 2);
    const int brow = warpN + (lane & 7) + ((lane >> 4) << 3);
    const uint32_t b_base = (uint32_t)CTILE_BYTES
        + (uint32_t)((brow * CROW + ((lane >> 3) & 1) * 8) * 2);

    float acc[2][2][4];
    #pragma unroll
    for (int mi = 0; mi < 2; mi++)
        #pragma unroll
        for (int ni = 0; ni < 2; ni++)
            #pragma unroll
            for (int r = 0; r < 4; r++) acc[mi][ni][r] = 0.f;

    const int nchunks = T / CT;            // 64

    auto load = [&](int ch) {
        const int t0 = ch * CT;
        const uint32_t sb = smem0 + (ch % CSTAGES) * CSTAGE_BYTES;
        #pragma unroll
        for (int i = 0; i < 4; i++) {
            int v = tid + i * 256;
            int mat = v >> 9;
            int r = (v >> 3) & 63;
            int c8 = (v & 7) * 8;
            const __half* gp = (mat ? vb : kb) + (long)r * T + t0 + c8;
            cp_async16(sb + (uint32_t)(mat * CTILE_BYTES + r * (CROW * 2) + c8 * 2),
                       gp);
        }
        cp_commit();
    };

    load(0); load(1); load(2);

    for (int ch = 0; ch < nchunks; ch++) {
        if (ch + 3 < nchunks) { load(ch + 3); cp_wait<3>(); }
        else {
            int rem = nchunks - 1 - ch;
            if (rem == 2) cp_wait<2>();
            else if (rem == 1) cp_wait<1>();
            else if (rem == 0) cp_wait<0>();
            else cp_wait<3>();
        }
        __syncthreads();

        const uint32_t sb = smem0 + (ch % CSTAGES) * CSTAGE_BYTES;
        #pragma unroll
        for (int kk = 0; kk < 4; kk++) {
            uint32_t afr[2][4], bfr4[4];
            #pragma unroll
            for (int mi = 0; mi < 2; mi++)
                ldsm_x4(afr[mi], sb + a_base
                        + (uint32_t)((mi * 16 * CROW + kk * 16) * 2));
            ldsm_x4(bfr4, sb + b_base + (uint32_t)(kk * 16 * 2));
            #pragma unroll
            for (int mi = 0; mi < 2; mi++) {
                mma16n8k16(acc[mi][0], afr[mi], &bfr4[0]);
                mma16n8k16(acc[mi][1], afr[mi], &bfr4[2]);
            }
        }
        __syncthreads();
    }

    float* cp = ctx + (long)bh * (DH * DH);
    #pragma unroll
    for (int mi = 0; mi < 2; mi++) {
        int d0 = warpM + mi * 16 + gid;
        #pragma unroll
        for (int ni = 0; ni < 2; ni++) {
            int e = warpN + ni * 8 + tg * 2;
            *(float2*)&cp[d0 * DH + e]       = make_float2(acc[mi][ni][0], acc[mi][ni][1]);
            *(float2*)&cp[(d0 + 8) * DH + e] = make_float2(acc[mi][ni][2], acc[mi][ni][3]);
        }
    }
}

// --------------------- fp32 -> fp16 convert pass ----------------------------
__global__ __launch_bounds__(256)
void conv_half(const float* __restrict__ in, __half* __restrict__ out, int n4)
{
    int i = blockIdx.x * 256 + threadIdx.x;
    if (i >= n4) return;
    float4 v = ((const float4*)in)[i];
    ((__half2*)out)[2 * i]     = __floats2half2_rn(v.x, v.y);
    ((__half2*)out)[2 * i + 1] = __floats2half2_rn(v.z, v.w);
}

// --------------------- softmax over time dim (k), fp16 in/out ---------------
__global__ __launch_bounds__(256)
void softmax_k(__half* __restrict__ kh)
{
    __shared__ float sm[32];
    int r = blockIdx.x;              // b*512 + c
    int b = r >> 9, c = r & 511;
    __half2* row = (__half2*)(kh + ((long)b * HID + c) * T);
    int tid = threadIdx.x;

    float v[16];
    float mx = -1e30f;
    #pragma unroll
    for (int i = 0; i < 8; i++) {
        float2 f = __half22float2(row[tid + i * 256]);
        v[2 * i] = f.x; v[2 * i + 1] = f.y;
        mx = fmaxf(mx, fmaxf(f.x, f.y));
    }
    mx = blockReduceMax(mx, sm);
    float s = 0.f;
    #pragma unroll
    for (int i = 0; i < 16; i++) { v[i] = __expf(v[i] - mx); s += v[i]; }
    s = blockReduceSum(s, sm);
    float inv = 1.f / s;
    #pragma unroll
    for (int i = 0; i < 8; i++)
        row[tid + i * 256] = __floats2half2_rn(v[2 * i] * inv, v[2 * i + 1] * inv);
}

// ----- Weff[b][o][h*64+d] = sum_e Wout[o][h*64+e] * ctx[b][h][d][e] -> half --
__global__ __launch_bounds__(256)
void make_weff(const float* __restrict__ ctx, const float* __restrict__ Wout,
               __half* __restrict__ weffh)
{
    __shared__ float cs[DH][DH];   // ctx[d][e]
    int b = blockIdx.x, h = blockIdx.y;
    const float* c = ctx + (long)(b * H + h) * (DH * DH);
    for (int i = threadIdx.x; i < DH * DH; i += 256) cs[i >> 6][i & 63] = c[i];
    __syncthreads();

    #pragma unroll
    for (int oo = 0; oo < 2; oo++) {
        int o = threadIdx.x + oo * 256;
        float w[DH];
        #pragma unroll
        for (int e = 0; e < DH; e++) w[e] = Wout[(long)o * C + h * DH + e];
        for (int d = 0; d < DH; d++) {
            float s = 0.f;
            #pragma unroll
            for (int e = 0; e < DH; e++) s = fmaf(w[e], cs[d][e], s);
            weffh[((long)b * C + o) * C + h * DH + d] = __float2half(s);
        }
    }
}

// --------------------- GroupNorm finalize + normalize -----------------------
__global__ __launch_bounds__(64)
void gn_finalize(const float* __restrict__ stats, float* __restrict__ mr)
{
    __shared__ float sm[32];
    int b = blockIdx.x;
    float s  = stats[(b * 64 + threadIdx.x) * 2 + 0];
    float ss = stats[(b * 64 + threadIdx.x) * 2 + 1];
    float S  = blockReduceSum(s, sm);
    float SS = blockReduceSum(ss, sm);
    if (threadIdx.x == 0) {
        const float n = (float)((long)C * T);
        float mean = S / n;
        float var  = SS / n - mean * mean;
        mr[b * 2 + 0] = mean;
        mr[b * 2 + 1] = rsqrtf(var + GN_EPS);
    }
}

__global__ __launch_bounds__(256)
void gn_norm(const __half* __restrict__ yh, const float* __restrict__ mr,
             const float* __restrict__ gw, const float* __restrict__ gb,
             float* __restrict__ out)
{
    int b = blockIdx.y;
    long base = (long)b * C * T;
    int idx = (blockIdx.x * 256 + threadIdx.x) * 4;
    int c = idx >> 12;                 // / 4096
    float mean = mr[b * 2 + 0], rstd = mr[b * 2 + 1];
    float g   = gw[c] * rstd;
    float beta = gb[c] - mean * g;
    float2 f0 = __half22float2(*(const __half2*)&yh[base + idx]);
    float2 f1 = __half22float2(*(const __half2*)&yh[base + idx + 2]);
    float4 v;
    v.x = fmaf(f0.x, g, beta);
    v.y = fmaf(f0.y, g, beta);
    v.z = fmaf(f1.x, g, beta);
    v.w = fmaf(f1.y, g, beta);
    *(float4*)&out[base + idx] = v;
}

// ---------------------------------------------------------------------------
extern "C" void kernel_launch(void* const* d_in, const int* in_sizes, int n_in,
                              void* d_out, int out_size)
{
    const float* x     = (const float*)d_in[0];
    const float* Wqkv  = (const float*)d_in[1];
    const float* Wout  = (const float*)d_in[2];
    const float* bout  = (const float*)d_in[3];
    const float* gnw   = (const float*)d_in[4];
    const float* gnb   = (const float*)d_in[5];
    float* out = (float*)d_out;

    float *ctx, *stats, *mr;
    __half *xh, *qh, *kh, *vh, *wqkvh, *weffh;
    cudaGetSymbolAddress((void**)&ctx,   g_ctx);
    cudaGetSymbolAddress((void**)&stats, g_stats);
    cudaGetSymbolAddress((void**)&mr,    g_mr);
    cudaGetSymbolAddress((void**)&xh,    g_xh);
    cudaGetSymbolAddress((void**)&qh,    g_qh);
    cudaGetSymbolAddress((void**)&kh,    g_kh);
    cudaGetSymbolAddress((void**)&vh,    g_vh);
    cudaGetSymbolAddress((void**)&wqkvh, g_wqkvh);
    cudaGetSymbolAddress((void**)&weffh, g_weffh);

    __half* yh = xh;   // xh dead after GEMM1; reuse as fp16 y

    cudaFuncSetAttribute(hgemm<1>,
                         cudaFuncAttributeMaxDynamicSharedMemorySize, TGEMM_SMEM);
    cudaFuncSetAttribute(hgemm<2>,
                         cudaFuncAttributeMaxDynamicSharedMemorySize, TGEMM_SMEM);
    cudaFuncSetAttribute(ctx_hmma,
                         cudaFuncAttributeMaxDynamicSharedMemorySize, CTX_SMEM);

    // Try to set up a side stream for GEMM1_q || (softmax_k -> ctx -> weff).
    // Graph-capture-safe fork/join via events; falls back to serial on failure.
    cudaStream_t s2 = 0;
    cudaEvent_t evA = 0, evB = 0;
    bool forked = (cudaStreamCreateWithFlags(&s2, cudaStreamNonBlocking) == cudaSuccess);
    if (forked) forked = (cudaEventCreateWithFlags(&evA, cudaEventDisableTiming) == cudaSuccess);
    if (forked) forked = (cudaEventCreateWithFlags(&evB, cudaEventDisableTiming) == cudaSuccess);

    // 0) convert inputs to fp16
    conv_half<<<(B * C * T / 4 + 255) / 256, 256>>>(x, xh, B * C * T / 4);
    conv_half<<<(QKV_CH * C / 4 + 255) / 256, 256>>>(Wqkv, wqkvh, QKV_CH * C / 4);

    // 1a) k/v portion of qkv GEMM (channels 512..1535)
    hgemm<1><<<dim3(T / BN, 8, B), 256, TGEMM_SMEM>>>(
        wqkvh, 0L, xh, (long)C * T, HID,
        QKV_CH, T, C, nullptr, qh, kh, vh, nullptr);

    if (forked) {
        cudaEventRecord(evA, 0);
        cudaStreamWaitEvent(s2, evA, 0);
        // 1b) q portion on side stream, concurrent with k-chain below
        hgemm<1><<<dim3(T / BN, 4, B), 256, TGEMM_SMEM, s2>>>(
            wqkvh, 0L, xh, (long)C * T, 0,
            QKV_CH, T, C, nullptr, qh, kh, vh, nullptr);
        cudaEventRecord(evB, s2);
    } else {
        hgemm<1><<<dim3(T / BN, 4, B), 256, TGEMM_SMEM>>>(
            wqkvh, 0L, xh, (long)C * T, 0,
            QKV_CH, T, C, nullptr, qh, kh, vh, nullptr);
    }

    // 2-4) k chain (depends only on kh/vh)
    softmax_k<<<B * HID, 256>>>(kh);
    ctx_hmma<<<B * H, 256, CTX_SMEM>>>(kh, vh, ctx);
    make_weff<<<dim3(B, H), 256>>>(ctx, Wout, weffh);

    if (forked) cudaStreamWaitEvent(0, evB, 0);

    // 5) y = Weff @ q + b_out (fp16 y into reused xh), fused GN partial stats
    hgemm<2><<<dim3(T / BN, C / BM, B), 256, TGEMM_SMEM>>>(
        weffh, (long)C * C, qh, (long)HID * T, 0,
        C, T, C, bout, yh, nullptr, nullptr, stats);

    // 6) GroupNorm finalize + apply
    gn_finalize<<<B, 64>>>(stats, mr);
    gn_norm<<<dim3((C * T) / 1024, B), 256>>>(yh, mr, gnw, gnb, out);
}

// round 14
// speedup vs baseline: 4.9198x; 1.0935x over previous
#include <cuda_runtime.h>
#include <cuda_fp16.h>
#include <cstdint>

// ---------------------------------------------------------------------------
// LinearAttention fused pipeline (fp16 HMMA GEMMs + HMMA ctx, fused softmax_q
// + GN stats; stream-forked GEMM1_q || softmax_k->ctx->weff chain).
// GEMM tile 128x128, occupancy 2 (was 1) to hide sync/load bubbles.
// b=16, c=512, t=4096, heads=8, dh=64, hidden=512
// ---------------------------------------------------------------------------

#define B   16
#define C   512
#define T   4096
#define H   8
#define DH  64
#define HID 512
#define QKV_CH 1536
#define SCALE 0.125f   // 64^-0.5
#define GN_EPS 1e-5f

// Scratch (static device arrays: allocation-free rule)
__device__ __half g_xh[(size_t)B * C * T];                // 67 MB (xh, then y fp16)
__device__ __half g_qh[(size_t)B * HID * T];              // 67 MB (softmaxed q)
__device__ __half g_kh[(size_t)B * HID * T];              // 67 MB
__device__ __half g_vh[(size_t)B * HID * T];              // 67 MB
__device__ __half g_wqkvh[(size_t)QKV_CH * C];            // 1.5 MB
__device__ __half g_weffh[(size_t)B * C * C];             // 8 MB
__device__ float  g_ctx[(size_t)B * H * DH * DH];         // 2 MB
__device__ float  g_stats[B * 128 * 2];
__device__ float  g_mr[B * 2];

// ========================= helpers =========================================
__device__ __forceinline__ uint32_t smem_u32(const void* p) {
    uint32_t a;
    asm("{ .reg .u64 t; cvta.to.shared.u64 t, %1; cvt.u32.u64 %0, t; }"
        : "=r"(a) : "l"(p));
    return a;
}

__device__ __forceinline__ void cp_async16(uint32_t smem_dst, const void* gsrc) {
    asm volatile("cp.async.cg.shared.global [%0], [%1], 16;"
                 :: "r"(smem_dst), "l"(gsrc));
}
__device__ __forceinline__ void cp_commit() {
    asm volatile("cp.async.commit_group;" ::: "memory");
}
template <int N>
__device__ __forceinline__ void cp_wait() {
    asm volatile("cp.async.wait_group %0;" :: "n"(N) : "memory");
}

__device__ __forceinline__ void ldsm_x4(uint32_t* r, uint32_t addr) {
    asm volatile("ldmatrix.sync.aligned.m8n8.x4.shared.b16 {%0,%1,%2,%3}, [%4];"
                 : "=r"(r[0]), "=r"(r[1]), "=r"(r[2]), "=r"(r[3]) : "r"(addr));
}
__device__ __forceinline__ void ldsm_x4_trans(uint32_t* r, uint32_t addr) {
    asm volatile("ldmatrix.sync.aligned.m8n8.x4.trans.shared.b16 {%0,%1,%2,%3}, [%4];"
                 : "=r"(r[0]), "=r"(r[1]), "=r"(r[2]), "=r"(r[3]) : "r"(addr));
}

__device__ __forceinline__ void mma16n8k16(float* c, const uint32_t* a,
                                           const uint32_t* b) {
    asm volatile(
        "mma.sync.aligned.m16n8k16.row.col.f32.f16.f16.f32 "
        "{%0,%1,%2,%3}, {%4,%5,%6,%7}, {%8,%9}, {%0,%1,%2,%3};"
        : "+f"(c[0]), "+f"(c[1]), "+f"(c[2]), "+f"(c[3])
        : "r"(a[0]), "r"(a[1]), "r"(a[2]), "r"(a[3]),
          "r"(b[0]), "r"(b[1]));
}

// ------------------------- block reduce helper -----------------------------
__device__ __forceinline__ float blockReduceSum(float v, float* sm) {
    __syncthreads();
    #pragma unroll
    for (int o = 16; o; o >>= 1) v += __shfl_down_sync(0xffffffffu, v, o);
    int lane = threadIdx.x & 31, w = threadIdx.x >> 5;
    if (lane == 0) sm[w] = v;
    __syncthreads();
    if (w == 0) {
        v = (lane < (int)(blockDim.x >> 5)) ? sm[lane] : 0.f;
        #pragma unroll
        for (int o = 16; o; o >>= 1) v += __shfl_down_sync(0xffffffffu, v, o);
        if (lane == 0) sm[0] = v;
    }
    __syncthreads();
    return sm[0];
}

__device__ __forceinline__ float blockReduceMax(float v, float* sm) {
    __syncthreads();
    #pragma unroll
    for (int o = 16; o; o >>= 1) v = fmaxf(v, __shfl_down_sync(0xffffffffu, v, o));
    int lane = threadIdx.x & 31, w = threadIdx.x >> 5;
    if (lane == 0) sm[w] = v;
    __syncthreads();
    if (w == 0) {
        v = (lane < (int)(blockDim.x >> 5)) ? sm[lane] : -1e30f;
        #pragma unroll
        for (int o = 16; o; o >>= 1) v = fmaxf(v, __shfl_down_sync(0xffffffffu, v, o));
        if (lane == 0) sm[0] = v;
    }
    __syncthreads();
    return sm[0];
}

// ========================= fp16 HMMA GEMM ==================================
// Tile 128x128x32, 8 warps (2m x 4n) of 64x32, 4-stage cp.async, occupancy 2.
#define BM 128
#define BN 128
#define BK 32
#define ASH 40     // halves per A row (pad 8)
#define BSH 136    // halves per B row (pad 8)
#define A_BYTES (BM * ASH * 2)            // 10240
#define B_BYTES (BK * BSH * 2)            // 8704
#define STAGE_BYTES (A_BYTES + B_BYTES)   // 18944
#define NSTAGE 4
#define TGEMM_SMEM (NSTAGE * STAGE_BYTES) // 75776

// MODE 1: qkv epilogue (q softmax -> qh, k/v -> kh/vh), rows offset by bm0.
// MODE 2: y fp16 -> q_out, bias, GN partial stats.
template <int MODE>
__global__ __launch_bounds__(256, 2)
void hgemm(const __half* __restrict__ A, long strideA,
           const __half* __restrict__ X, long strideX,
           int bm0,
           int M, int N, int K, const float* __restrict__ bias,
           __half* __restrict__ q_out, __half* __restrict__ k_out,
           __half* __restrict__ v_out, float* __restrict__ stats)
{
    extern __shared__ char dsm[];
    __shared__ float redsm[32];
    const int tid = threadIdx.x;
    const int wid = tid >> 5;
    const int lane = tid & 31;
    const int gid = lane >> 2;
    const int tg  = lane & 3;
    const int lg  = lane >> 3;
    const int lr  = lane & 7;
    const int b  = blockIdx.z;
    const int bm = bm0 + blockIdx.y * BM, bn = blockIdx.x * BN;
    const __half* Ab = A + (long)b * strideA + (long)bm * K;
    const __half* Xb = X + (long)b * strideX + bn;

    const uint32_t smem0 = smem_u32(dsm);
    const int warpM = (wid >> 2) * 64;     // 0 or 64
    const int warpN = (wid & 3) * 32;      // 0,32,64,96

    const uint32_t a_ldsm = (uint32_t)(((warpM + (lg & 1) * 8 + lr) * ASH
                                        + (lg >> 1) * 8) * 2);
    const uint32_t b_ldsm = (uint32_t)A_BYTES
        + (uint32_t)((((lg & 1) * 8 + lr) * BSH + warpN + (lg >> 1) * 8) * 2);

    float acc[4][4][4];
    #pragma unroll
    for (int mt = 0; mt < 4; mt++)
        #pragma unroll
        for (int nt = 0; nt < 4; nt++)
            #pragma unroll
            for (int r = 0; r < 4; r++) acc[mt][nt][r] = 0.f;

    const int niter = K / BK;   // 16

    auto load_stage = [&](int it) {
        const int k0 = it * BK;
        const uint32_t sb = smem0 + (it % NSTAGE) * STAGE_BYTES;
        #pragma unroll
        for (int i = 0; i < 2; i++) {          // A: 512 chunks of 8 halves
            int v = tid + i * 256;
            int row = v >> 2, c8 = (v & 3) * 8;
            cp_async16(sb + (uint32_t)((row * ASH + c8) * 2),
                       &Ab[(long)row * K + k0 + c8]);
        }
        #pragma unroll
        for (int i = 0; i < 2; i++) {          // B: 512 chunks
            int v = tid + i * 256;
            int kr = v >> 4, c8 = (v & 15) * 8;
            cp_async16(sb + (uint32_t)A_BYTES + (uint32_t)((kr * BSH + c8) * 2),
                       &Xb[(long)(k0 + kr) * N + c8]);
        }
        cp_commit();
    };

    load_stage(0);
    load_stage(1);
    load_stage(2);

    for (int it = 0; it < niter; it++) {
        if (it + 3 < niter) { load_stage(it + 3); cp_wait<3>(); }
        else {
            int rem = niter - 1 - it;
            if (rem >= 3) cp_wait<3>();
            else if (rem == 2) cp_wait<2>();
            else if (rem == 1) cp_wait<1>();
            else cp_wait<0>();
        }
        __syncthreads();

        const uint32_t sb = smem0 + (it % NSTAGE) * STAGE_BYTES;

        #pragma unroll
        for (int kk = 0; kk < 2; kk++) {
            uint32_t afr[4][4], bfr[4][2];
            #pragma unroll
            for (int mt = 0; mt < 4; mt++)
                ldsm_x4(afr[mt], sb + a_ldsm
                        + (uint32_t)((mt * 16 * ASH + kk * 16) * 2));
            #pragma unroll
            for (int p = 0; p < 2; p++) {
                uint32_t r4[4];
                ldsm_x4_trans(r4, sb + b_ldsm
                              + (uint32_t)((kk * 16 * BSH + p * 16) * 2));
                bfr[2 * p][0] = r4[0]; bfr[2 * p][1] = r4[1];
                bfr[2 * p + 1][0] = r4[2]; bfr[2 * p + 1][1] = r4[3];
            }
            #pragma unroll
            for (int mt = 0; mt < 4; mt++)
                #pragma unroll
                for (int nt = 0; nt < 4; nt++)
                    mma16n8k16(acc[mt][nt], afr[mt], bfr[nt]);
        }
        __syncthreads();
    }

    if (MODE == 1) {
        const int ch0 = bm + warpM;
        if (ch0 < HID) {
            float mxA[4], mxB[4], scA[4], scB[4];
            #pragma unroll
            for (int nt = 0; nt < 4; nt++) {
                float a = -1e30f, bb = -1e30f;
                #pragma unroll
                for (int mt = 0; mt < 4; mt++) {
                    a  = fmaxf(a,  fmaxf(acc[mt][nt][0], acc[mt][nt][2]));
                    bb = fmaxf(bb, fmaxf(acc[mt][nt][1], acc[mt][nt][3]));
                }
                #pragma unroll
                for (int o = 4; o <= 16; o <<= 1) {
                    a  = fmaxf(a,  __shfl_xor_sync(0xffffffffu, a, o));
                    bb = fmaxf(bb, __shfl_xor_sync(0xffffffffu, bb, o));
                }
                mxA[nt] = a; mxB[nt] = bb;
            }
            #pragma unroll
            for (int nt = 0; nt < 4; nt++) {
                float sa = 0.f, sb2 = 0.f;
                #pragma unroll
                for (int mt = 0; mt < 4; mt++) {
                    acc[mt][nt][0] = __expf(acc[mt][nt][0] - mxA[nt]);
                    acc[mt][nt][2] = __expf(acc[mt][nt][2] - mxA[nt]);
                    sa += acc[mt][nt][0] + acc[mt][nt][2];
                    acc[mt][nt][1] = __expf(acc[mt][nt][1] - mxB[nt]);
                    acc[mt][nt][3] = __expf(acc[mt][nt][3] - mxB[nt]);
                    sb2 += acc[mt][nt][1] + acc[mt][nt][3];
                }
                #pragma unroll
                for (int o = 4; o <= 16; o <<= 1) {
                    sa  += __shfl_xor_sync(0xffffffffu, sa, o);
                    sb2 += __shfl_xor_sync(0xffffffffu, sb2, o);
                }
                scA[nt] = SCALE / sa; scB[nt] = SCALE / sb2;
            }
            __half* qb = q_out + (long)b * HID * T;
            #pragma unroll
            for (int mt = 0; mt < 4; mt++) {
                int ch = ch0 + mt * 16 + gid;
                #pragma unroll
                for (int nt = 0; nt < 4; nt++) {
                    int t = bn + warpN + nt * 8 + tg * 2;
                    *(__half2*)&qb[(long)ch * T + t] =
                        __floats2half2_rn(acc[mt][nt][0] * scA[nt],
                                          acc[mt][nt][1] * scB[nt]);
                    *(__half2*)&qb[(long)(ch + 8) * T + t] =
                        __floats2half2_rn(acc[mt][nt][2] * scA[nt],
                                          acc[mt][nt][3] * scB[nt]);
                }
            }
        } else {
            __half* dst = (ch0 < 2 * HID) ? k_out : v_out;
            const int chbase = ch0 - ((ch0 < 2 * HID) ? HID : 2 * HID);
            __half* db = dst + (long)b * HID * T;
            #pragma unroll
            for (int mt = 0; mt < 4; mt++) {
                int ch = chbase + mt * 16 + gid;
                #pragma unroll
                for (int nt = 0; nt < 4; nt++) {
                    int t = bn + warpN + nt * 8 + tg * 2;
                    *(__half2*)&db[(long)ch * T + t] =
                        __floats2half2_rn(acc[mt][nt][0], acc[mt][nt][1]);
                    *(__half2*)&db[(long)(ch + 8) * T + t] =
                        __floats2half2_rn(acc[mt][nt][2], acc[mt][nt][3]);
                }
            }
        }
    } else {
        // ---- GEMM2 epilogue: y fp16 + bias, GN partial sums (fp32) ----
        float ls = 0.f, lss = 0.f;
        __half* yb = q_out + (long)b * C * T;
        #pragma unroll
        for (int mt = 0; mt < 4; mt++) {
            int row0 = bm + warpM + mt * 16 + gid;
            float bv0 = bias[row0];
            float bv1 = bias[row0 + 8];
            #pragma unroll
            for (int nt = 0; nt < 4; nt++) {
                int col = bn + warpN + nt * 8 + tg * 2;
                float o0x = acc[mt][nt][0] + bv0, o0y = acc[mt][nt][1] + bv0;
                float o1x = acc[mt][nt][2] + bv1, o1y = acc[mt][nt][3] + bv1;
                ls  += o0x + o0y + o1x + o1y;
                lss += o0x * o0x + o0y * o0y + o1x * o1x + o1y * o1y;
                *(__half2*)&yb[(long)row0 * T + col] = __floats2half2_rn(o0x, o0y);
                *(__half2*)&yb[(long)(row0 + 8) * T + col] = __floats2half2_rn(o1x, o1y);
            }
        }
        float S  = blockReduceSum(ls, redsm);
        float SS = blockReduceSum(lss, redsm);
        if (tid == 0) {
            int tile = blockIdx.y * gridDim.x + blockIdx.x;   // < 128
            stats[((long)b * 128 + tile) * 2 + 0] = S;
            stats[((long)b * 128 + tile) * 2 + 1] = SS;
        }
    }
}

// ================= HMMA context: ctx[b,h] = k @ v^T (64x64) ================
#define CT 64
#define CROW 72
#define CTILE_BYTES (DH * CROW * 2)        // 9216
#define CSTAGE_BYTES (2 * CTILE_BYTES)     // 18432
#define CSTAGES 4
#define CTX_SMEM (CSTAGES * CSTAGE_BYTES)  // 73728

__global__ __launch_bounds__(256, 1)
void ctx_hmma(const __half* __restrict__ kh, const __half* __restrict__ vh,
              float* __restrict__ ctx)
{
    extern __shared__ char dsm[];
    const int tid = threadIdx.x;
    const int wid = tid >> 5;
    const int lane = tid & 31;
    const int gid = lane >> 2;
    const int tg  = lane & 3;
    const int lg  = lane >> 3;
    const int lr  = lane & 7;
    const int bh = blockIdx.x;
    const int b = bh >> 3, h = bh & 7;
    const __half* kb = kh + ((long)b * HID + h * DH) * T;
    const __half* vb = vh + ((long)b * HID + h * DH) * T;

    const uint32_t smem0 = smem_u32(dsm);
    const int warpM = (wid >> 2) * 32;
    const int warpN = (wid & 3) * 16;

    const uint32_t a_base = (uint32_t)(((warpM + (lg & 1) * 8 + lr) * CROW
                                        + (lg >> 1) * 8) * 2);
    const int brow = warpN + (lane & 7) + ((lane >> 4) << 3);
    const uint32_t b_base = (uint32_t)CTILE_BYTES
        + (uint32_t)((brow * CROW + ((lane >> 3) & 1) * 8) * 2);

    float acc[2][2][4];
    #pragma unroll
    for (int mi = 0; mi < 2; mi++)
        #pragma unroll
        for (int ni = 0; ni < 2; ni++)
            #pragma unroll
            for (int r = 0; r < 4; r++) acc[mi][ni][r] = 0.f;

    const int nchunks = T / CT;            // 64

    auto load = [&](int ch) {
        const int t0 = ch * CT;
        const uint32_t sb = smem0 + (ch % CSTAGES) * CSTAGE_BYTES;
        #pragma unroll
        for (int i = 0; i < 4; i++) {
            int v = tid + i * 256;
            int mat = v >> 9;
            int r = (v >> 3) & 63;
            int c8 = (v & 7) * 8;
            const __half* gp = (mat ? vb : kb) + (long)r * T + t0 + c8;
            cp_async16(sb + (uint32_t)(mat * CTILE_BYTES + r * (CROW * 2) + c8 * 2),
                       gp);
        }
        cp_commit();
    };

    load(0); load(1); load(2);

    for (int ch = 0; ch < nchunks; ch++) {
        if (ch + 3 < nchunks) { load(ch + 3); cp_wait<3>(); }
        else {
            int rem = nchunks - 1 - ch;
            if (rem == 2) cp_wait<2>();
            else if (rem == 1) cp_wait<1>();
            else if (rem == 0) cp_wait<0>();
            else cp_wait<3>();
        }
        __syncthreads();

        const uint32_t sb = smem0 + (ch % CSTAGES) * CSTAGE_BYTES;
        #pragma unroll
        for (int kk = 0; kk < 4; kk++) {
            uint32_t afr[2][4], bfr4[4];
            #pragma unroll
            for (int mi = 0; mi < 2; mi++)
                ldsm_x4(afr[mi], sb + a_base
                        + (uint32_t)((mi * 16 * CROW + kk * 16) * 2));
            ldsm_x4(bfr4, sb + b_base + (uint32_t)(kk * 16 * 2));
            #pragma unroll
            for (int mi = 0; mi < 2; mi++) {
                mma16n8k16(acc[mi][0], afr[mi], &bfr4[0]);
                mma16n8k16(acc[mi][1], afr[mi], &bfr4[2]);
            }
        }
        __syncthreads();
    }

    float* cp = ctx + (long)bh * (DH * DH);
    #pragma unroll
    for (int mi = 0; mi < 2; mi++) {
        int d0 = warpM + mi * 16 + gid;
        #pragma unroll
        for (int ni = 0; ni < 2; ni++) {
            int e = warpN + ni * 8 + tg * 2;
            *(float2*)&cp[d0 * DH + e]       = make_float2(acc[mi][ni][0], acc[mi][ni][1]);
            *(float2*)&cp[(d0 + 8) * DH + e] = make_float2(acc[mi][ni][2], acc[mi][ni][3]);
        }
    }
}

// --------------------- fp32 -> fp16 convert pass ----------------------------
__global__ __launch_bounds__(256)
void conv_half(const float* __restrict__ in, __half* __restrict__ out, int n4)
{
    int i = blockIdx.x * 256 + threadIdx.x;
    if (i >= n4) return;
    float4 v = ((const float4*)in)[i];
    ((__half2*)out)[2 * i]     = __floats2half2_rn(v.x, v.y);
    ((__half2*)out)[2 * i + 1] = __floats2half2_rn(v.z, v.w);
}

// --------------------- softmax over time dim (k), fp16 in/out ---------------
__global__ __launch_bounds__(256)
void softmax_k(__half* __restrict__ kh)
{
    __shared__ float sm[32];
    int r = blockIdx.x;              // b*512 + c
    int b = r >> 9, c = r & 511;
    __half2* row = (__half2*)(kh + ((long)b * HID + c) * T);
    int tid = threadIdx.x;

    float v[16];
    float mx = -1e30f;
    #pragma unroll
    for (int i = 0; i < 8; i++) {
        float2 f = __half22float2(row[tid + i * 256]);
        v[2 * i] = f.x; v[2 * i + 1] = f.y;
        mx = fmaxf(mx, fmaxf(f.x, f.y));
    }
    mx = blockReduceMax(mx, sm);
    float s = 0.f;
    #pragma unroll
    for (int i = 0; i < 16; i++) { v[i] = __expf(v[i] - mx); s += v[i]; }
    s = blockReduceSum(s, sm);
    float inv = 1.f / s;
    #pragma unroll
    for (int i = 0; i < 8; i++)
        row[tid + i * 256] = __floats2half2_rn(v[2 * i] * inv, v[2 * i + 1] * inv);
}

// ----- Weff[b][o][h*64+d] = sum_e Wout[o][h*64+e] * ctx[b][h][d][e] -> half --
__global__ __launch_bounds__(256)
void make_weff(const float* __restrict__ ctx, const float* __restrict__ Wout,
               __half* __restrict__ weffh)
{
    __shared__ float cs[DH][DH];   // ctx[d][e]
    int b = blockIdx.x, h = blockIdx.y;
    const float* c = ctx + (long)(b * H + h) * (DH * DH);
    for (int i = threadIdx.x; i < DH * DH; i += 256) cs[i >> 6][i & 63] = c[i];
    __syncthreads();

    #pragma unroll
    for (int oo = 0; oo < 2; oo++) {
        int o = threadIdx.x + oo * 256;
        float w[DH];
        #pragma unroll
        for (int e = 0; e < DH; e++) w[e] = Wout[(long)o * C + h * DH + e];
        for (int d = 0; d < DH; d++) {
            float s = 0.f;
            #pragma unroll
            for (int e = 0; e < DH; e++) s = fmaf(w[e], cs[d][e], s);
            weffh[((long)b * C + o) * C + h * DH + d] = __float2half(s);
        }
    }
}

// --------------------- GroupNorm finalize + normalize -----------------------
__global__ __launch_bounds__(128)
void gn_finalize(const float* __restrict__ stats, float* __restrict__ mr)
{
    __shared__ float sm[32];
    int b = blockIdx.x;
    float s  = stats[(b * 128 + threadIdx.x) * 2 + 0];
    float ss = stats[(b * 128 + threadIdx.x) * 2 + 1];
    float S  = blockReduceSum(s, sm);
    float SS = blockReduceSum(ss, sm);
    if (threadIdx.x == 0) {
        const float n = (float)((long)C * T);
        float mean = S / n;
        float var  = SS / n - mean * mean;
        mr[b * 2 + 0] = mean;
        mr[b * 2 + 1] = rsqrtf(var + GN_EPS);
    }
}

__global__ __launch_bounds__(256)
void gn_norm(const __half* __restrict__ yh, const float* __restrict__ mr,
             const float* __restrict__ gw, const float* __restrict__ gb,
             float* __restrict__ out)
{
    int b = blockIdx.y;
    long base = (long)b * C * T;
    int idx = (blockIdx.x * 256 + threadIdx.x) * 4;
    int c = idx >> 12;                 // / 4096
    float mean = mr[b * 2 + 0], rstd = mr[b * 2 + 1];
    float g   = gw[c] * rstd;
    float beta = gb[c] - mean * g;
    float2 f0 = __half22float2(*(const __half2*)&yh[base + idx]);
    float2 f1 = __half22float2(*(const __half2*)&yh[base + idx + 2]);
    float4 v;
    v.x = fmaf(f0.x, g, beta);
    v.y = fmaf(f0.y, g, beta);
    v.z = fmaf(f1.x, g, beta);
    v.w = fmaf(f1.y, g, beta);
    *(float4*)&out[base + idx] = v;
}

// ---------------------------------------------------------------------------
extern "C" void kernel_launch(void* const* d_in, const int* in_sizes, int n_in,
                              void* d_out, int out_size)
{
    const float* x     = (const float*)d_in[0];
    const float* Wqkv  = (const float*)d_in[1];
    const float* Wout  = (const float*)d_in[2];
    const float* bout  = (const float*)d_in[3];
    const float* gnw   = (const float*)d_in[4];
    const float* gnb   = (const float*)d_in[5];
    float* out = (float*)d_out;

    float *ctx, *stats, *mr;
    __half *xh, *qh, *kh, *vh, *wqkvh, *weffh;
    cudaGetSymbolAddress((void**)&ctx,   g_ctx);
    cudaGetSymbolAddress((void**)&stats, g_stats);
    cudaGetSymbolAddress((void**)&mr,    g_mr);
    cudaGetSymbolAddress((void**)&xh,    g_xh);
    cudaGetSymbolAddress((void**)&qh,    g_qh);
    cudaGetSymbolAddress((void**)&kh,    g_kh);
    cudaGetSymbolAddress((void**)&vh,    g_vh);
    cudaGetSymbolAddress((void**)&wqkvh, g_wqkvh);
    cudaGetSymbolAddress((void**)&weffh, g_weffh);

    __half* yh = xh;   // xh dead after GEMM1; reuse as fp16 y

    cudaFuncSetAttribute(hgemm<1>,
                         cudaFuncAttributeMaxDynamicSharedMemorySize, TGEMM_SMEM);
    cudaFuncSetAttribute(hgemm<2>,
                         cudaFuncAttributeMaxDynamicSharedMemorySize, TGEMM_SMEM);
    cudaFuncSetAttribute(ctx_hmma,
                         cudaFuncAttributeMaxDynamicSharedMemorySize, CTX_SMEM);

    // side stream for GEMM1_q || (softmax_k -> ctx -> weff); serial fallback
    cudaStream_t s2 = 0;
    cudaEvent_t evA = 0, evB = 0;
    bool forked = (cudaStreamCreateWithFlags(&s2, cudaStreamNonBlocking) == cudaSuccess);
    if (forked) forked = (cudaEventCreateWithFlags(&evA, cudaEventDisableTiming) == cudaSuccess);
    if (forked) forked = (cudaEventCreateWithFlags(&evB, cudaEventDisableTiming) == cudaSuccess);

    // 0) convert inputs to fp16
    conv_half<<<(B * C * T / 4 + 255) / 256, 256>>>(x, xh, B * C * T / 4);
    conv_half<<<(QKV_CH * C / 4 + 255) / 256, 256>>>(Wqkv, wqkvh, QKV_CH * C / 4);

    // 1a) k/v portion of qkv GEMM (channels 512..1535)
    hgemm<1><<<dim3(T / BN, 8, B), 256, TGEMM_SMEM>>>(
        wqkvh, 0L, xh, (long)C * T, HID,
        QKV_CH, T, C, nullptr, qh, kh, vh, nullptr);

    if (forked) {
        cudaEventRecord(evA, 0);
        cudaStreamWaitEvent(s2, evA, 0);
        hgemm<1><<<dim3(T / BN, 4, B), 256, TGEMM_SMEM, s2>>>(
            wqkvh, 0L, xh, (long)C * T, 0,
            QKV_CH, T, C, nullptr, qh, kh, vh, nullptr);
        cudaEventRecord(evB, s2);
    } else {
        hgemm<1><<<dim3(T / BN, 4, B), 256, TGEMM_SMEM>>>(
            wqkvh, 0L, xh, (long)C * T, 0,
            QKV_CH, T, C, nullptr, qh, kh, vh, nullptr);
    }

    // 2-4) k chain (depends only on kh/vh)
    softmax_k<<<B * HID, 256>>>(kh);
    ctx_hmma<<<B * H, 256, CTX_SMEM>>>(kh, vh, ctx);
    make_weff<<<dim3(B, H), 256>>>(ctx, Wout, weffh);

    if (forked) cudaStreamWaitEvent(0, evB, 0);

    // 5) y = Weff @ q + b_out (fp16 y into reused xh), fused GN partial stats
    hgemm<2><<<dim3(T / BN, C / BM, B), 256, TGEMM_SMEM>>>(
        weffh, (long)C * C, qh, (long)HID * T, 0,
        C, T, C, bout, yh, nullptr, nullptr, stats);

    // 6) GroupNorm finalize + apply
    gn_finalize<<<B, 128>>>(stats, mr);
    gn_norm<<<dim3((C * T) / 1024, B), 256>>>(yh, mr, gnw, gnb, out);
}